// round 2
// baseline (speedup 1.0000x reference)
#include <cuda_runtime.h>
#include <stdint.h>

// Problem constants
#define BB 2
#define SS 2048
#define DD 1024
#define HH 16
#define DH 64
#define MM (BB*SS)   // 4096 rows for all GEMMs

// Scratch (no cudaMalloc allowed)
__device__ float g_q[(size_t)BB*HH*SS*DH];    // [B,H,S,dh]
__device__ float g_k[(size_t)BB*HH*SS*DH];
__device__ float g_v[(size_t)BB*HH*SS*DH];
__device__ float g_ctx[(size_t)MM*DD];        // [B,S,D] combined heads
__device__ int   g_mask_kind;                 // 0=byte, 1=int32, 2=float32

// ---------------------------------------------------------------------------
// Mask dtype detection: read first 8 32-bit words (safe: mask >= 8.4MB).
// int32 0/1 -> kind 1 ; float 0.0/1.0 -> kind 2 ; else bytes -> kind 0.
// Deterministic for fixed inputs; graph-capturable.
// ---------------------------------------------------------------------------
__global__ void detect_mask_kind_kernel(const unsigned int* __restrict__ m) {
    if (threadIdx.x == 0) {
        bool isInt = true, isFloat = true;
        #pragma unroll
        for (int i = 0; i < 8; i++) {
            unsigned v = m[i];
            if (v != 0u && v != 1u) isInt = false;
            if (v != 0u && v != 0x3f800000u) isFloat = false;
        }
        g_mask_kind = isInt ? 1 : (isFloat ? 2 : 0);
    }
}

// ---------------------------------------------------------------------------
// GEMM: C = scale * (A @ W^T) [+ bias]
//   A: [MM, DD] row-major, W: [DD, DD] row-major (W[n][k]), both K-contiguous.
//   MODE 0: split-head store into [B,H,S,dh] scratch (for q/k/v)
//   MODE 1: plain [MM, DD] store with bias (for output projection)
// Block tile 128x128x16, 256 threads, 8x8 microtile.
// ---------------------------------------------------------------------------
template <int MODE>
__global__ void __launch_bounds__(256) gemm_nt_kernel(
    const float* __restrict__ A, const float* __restrict__ W,
    const float* __restrict__ bias, float* __restrict__ C, float scale)
{
    __shared__ __align__(16) float As[16][128];
    __shared__ __align__(16) float Bs[16][128];

    const int t  = threadIdx.x;
    const int m0 = blockIdx.y * 128;
    const int n0 = blockIdx.x * 128;
    const int tm = (t >> 4) * 8;
    const int tn = (t & 15) * 8;

    float acc[8][8];
    #pragma unroll
    for (int i = 0; i < 8; i++)
        #pragma unroll
        for (int j = 0; j < 8; j++) acc[i][j] = 0.f;

    for (int k0 = 0; k0 < DD; k0 += 16) {
        #pragma unroll
        for (int i = 0; i < 2; i++) {
            int id  = i * 256 + t;          // 0..511
            int row = id >> 2;
            int kv  = (id & 3) * 4;
            float4 a = *(const float4*)&A[(size_t)(m0 + row) * DD + k0 + kv];
            As[kv + 0][row] = a.x; As[kv + 1][row] = a.y;
            As[kv + 2][row] = a.z; As[kv + 3][row] = a.w;
            float4 b = *(const float4*)&W[(size_t)(n0 + row) * DD + k0 + kv];
            Bs[kv + 0][row] = b.x; Bs[kv + 1][row] = b.y;
            Bs[kv + 2][row] = b.z; Bs[kv + 3][row] = b.w;
        }
        __syncthreads();

        #pragma unroll
        for (int k = 0; k < 16; k++) {
            float4 a0 = *(const float4*)&As[k][tm];
            float4 a1 = *(const float4*)&As[k][tm + 4];
            float4 b0 = *(const float4*)&Bs[k][tn];
            float4 b1 = *(const float4*)&Bs[k][tn + 4];
            float av[8] = {a0.x, a0.y, a0.z, a0.w, a1.x, a1.y, a1.z, a1.w};
            float bv[8] = {b0.x, b0.y, b0.z, b0.w, b1.x, b1.y, b1.z, b1.w};
            #pragma unroll
            for (int i = 0; i < 8; i++)
                #pragma unroll
                for (int j = 0; j < 8; j++)
                    acc[i][j] += av[i] * bv[j];
        }
        __syncthreads();
    }

    if (MODE == 0) {
        // split heads: row m=(b,s), col n=(h,dd)
        #pragma unroll
        for (int i = 0; i < 8; i++) {
            int m = m0 + tm + i;
            int b = m >> 11;          // /SS
            int s = m & (SS - 1);
            #pragma unroll
            for (int j = 0; j < 8; j++) {
                int n  = n0 + tn + j;
                int h  = n >> 6;      // /DH
                int dd = n & (DH - 1);
                C[(((size_t)(b * HH + h) * SS + s) * DH) + dd] = acc[i][j] * scale;
            }
        }
    } else {
        #pragma unroll
        for (int i = 0; i < 8; i++) {
            int m = m0 + tm + i;
            #pragma unroll
            for (int j = 0; j < 8; j++) {
                int n = n0 + tn + j;
                C[(size_t)m * DD + n] = acc[i][j] * scale + bias[n];
            }
        }
    }
}

// ---------------------------------------------------------------------------
// Flash attention: one block per (b*H+h, q-tile of 64). 256 threads.
// Each thread owns a 4x4 score microtile (tr row-group 0..15, tc col-group
// 0..15) and a 4x4 output microtile (rows tr*4.., dims tc*4..).
// Online softmax with 16-lane shuffle reductions per row.
// ---------------------------------------------------------------------------
#define ATTN_SMEM_FLOATS (64*64 + 64*65 + 64*64 + 64*65)
#define ATTN_SMEM_BYTES  (ATTN_SMEM_FLOATS * 4)

__global__ void __launch_bounds__(256) attn_kernel(
    const float* __restrict__ Q, const float* __restrict__ K,
    const float* __restrict__ V, const uint8_t* __restrict__ mask8,
    float* __restrict__ ctx)
{
    extern __shared__ float sm[];
    float* Qs = sm;                    // [64][64]
    float* Ks = Qs + 64 * 64;          // [64][65] (padded: row-index varies across lanes)
    float* Vs = Ks + 64 * 65;          // [64][64]
    float* Ps = Vs + 64 * 64;          // [64][65]

    const int t  = threadIdx.x;
    const int bh = blockIdx.y;         // b*HH + h
    const int b  = bh >> 4;
    const int h  = bh & 15;
    const int q0 = blockIdx.x * 64;
    const int tr = t >> 4;             // 0..15
    const int tc = t & 15;             // 0..15

    const int mkind = g_mask_kind;
    const int*   mask32 = (const int*)mask8;
    const float* maskf  = (const float*)mask8;

    const float* Qbh = Q + (size_t)bh * SS * DH;
    const float* Kbh = K + (size_t)bh * SS * DH;
    const float* Vbh = V + (size_t)bh * SS * DH;

    // Load Q tile (coalesced)
    #pragma unroll
    for (int i = 0; i < 16; i++) {
        int idx = i * 256 + t;
        int r = idx >> 6, d = idx & 63;
        Qs[r * 64 + d] = Qbh[(size_t)(q0 + r) * DH + d];
    }

    float m_i[4], l_i[4], o_acc[4][4];
    #pragma unroll
    for (int i = 0; i < 4; i++) {
        m_i[i] = -1e30f; l_i[i] = 0.f;
        #pragma unroll
        for (int j = 0; j < 4; j++) o_acc[i][j] = 0.f;
    }
    __syncthreads();

    for (int k0 = 0; k0 < SS; k0 += 64) {
        // Load K, V tiles (coalesced)
        #pragma unroll
        for (int i = 0; i < 16; i++) {
            int idx = i * 256 + t;
            int r = idx >> 6, d = idx & 63;
            Ks[r * 65 + d] = Kbh[(size_t)(k0 + r) * DH + d];
            Vs[r * 64 + d] = Vbh[(size_t)(k0 + r) * DH + d];
        }
        // Mask for my 4x4 scores
        bool msk[4][4];
        #pragma unroll
        for (int i = 0; i < 4; i++) {
            size_t mrow = ((size_t)b * SS + (q0 + tr * 4 + i)) * SS + k0 + tc * 4;
            #pragma unroll
            for (int j = 0; j < 4; j++) {
                size_t mi = mrow + j;
                msk[i][j] = (mkind == 1) ? (mask32[mi] != 0)
                          : (mkind == 2) ? (maskf[mi] != 0.f)
                                         : (mask8[mi] != 0);
            }
        }
        __syncthreads();

        // Scores: s[i][j] = sum_d Q[tr*4+i][d] * K[tc*4+j][d]
        float s[4][4];
        #pragma unroll
        for (int i = 0; i < 4; i++)
            #pragma unroll
            for (int j = 0; j < 4; j++) s[i][j] = 0.f;
        #pragma unroll 8
        for (int d = 0; d < 64; d++) {
            float av[4], bv[4];
            #pragma unroll
            for (int i = 0; i < 4; i++) av[i] = Qs[(tr * 4 + i) * 64 + d];
            #pragma unroll
            for (int j = 0; j < 4; j++) bv[j] = Ks[(tc * 4 + j) * 65 + d];
            #pragma unroll
            for (int i = 0; i < 4; i++)
                #pragma unroll
                for (int j = 0; j < 4; j++)
                    s[i][j] += av[i] * bv[j];
        }
        #pragma unroll
        for (int i = 0; i < 4; i++)
            #pragma unroll
            for (int j = 0; j < 4; j++)
                if (msk[i][j]) s[i][j] = -1e30f;

        // Online softmax update (row group = 16 consecutive lanes)
        float p[4][4];
        #pragma unroll
        for (int i = 0; i < 4; i++) {
            float tmax = s[i][0];
            #pragma unroll
            for (int j = 1; j < 4; j++) tmax = fmaxf(tmax, s[i][j]);
            #pragma unroll
            for (int delta = 1; delta < 16; delta <<= 1)
                tmax = fmaxf(tmax, __shfl_xor_sync(0xFFFFFFFFu, tmax, delta));
            float mn = fmaxf(m_i[i], tmax);
            float corr = __expf(m_i[i] - mn);
            float rs = 0.f;
            #pragma unroll
            for (int j = 0; j < 4; j++) {
                float pv = (s[i][j] <= -1e29f) ? 0.f : __expf(s[i][j] - mn);
                p[i][j] = pv;
                rs += pv;
            }
            #pragma unroll
            for (int delta = 1; delta < 16; delta <<= 1)
                rs += __shfl_xor_sync(0xFFFFFFFFu, rs, delta);
            l_i[i] = l_i[i] * corr + rs;
            m_i[i] = mn;
            #pragma unroll
            for (int j = 0; j < 4; j++) o_acc[i][j] *= corr;
        }

        // Publish P tile
        #pragma unroll
        for (int i = 0; i < 4; i++)
            #pragma unroll
            for (int j = 0; j < 4; j++)
                Ps[(tr * 4 + i) * 65 + tc * 4 + j] = p[i][j];
        __syncthreads();

        // PV: o[i][jd] += sum_c P[tr*4+i][c] * V[c][tc*4+jd]
        #pragma unroll 8
        for (int c = 0; c < 64; c++) {
            float pa[4], vb[4];
            #pragma unroll
            for (int i = 0; i < 4; i++) pa[i] = Ps[(tr * 4 + i) * 65 + c];
            #pragma unroll
            for (int j = 0; j < 4; j++) vb[j] = Vs[c * 64 + tc * 4 + j];
            #pragma unroll
            for (int i = 0; i < 4; i++)
                #pragma unroll
                for (int j = 0; j < 4; j++)
                    o_acc[i][j] += pa[i] * vb[j];
        }
        __syncthreads();  // protect Ks/Vs/Ps before next tile's loads
    }

    // Epilogue: normalize and write combined-head ctx [B,S,D]
    #pragma unroll
    for (int i = 0; i < 4; i++) {
        float inv = (l_i[i] > 0.f) ? (1.f / l_i[i]) : 0.f;
        float4 o4;
        o4.x = o_acc[i][0] * inv; o4.y = o_acc[i][1] * inv;
        o4.z = o_acc[i][2] * inv; o4.w = o_acc[i][3] * inv;
        size_t oi = ((size_t)(b * SS + q0 + tr * 4 + i)) * DD + h * DH + tc * 4;
        *(float4*)&ctx[oi] = o4;
    }
}

// ---------------------------------------------------------------------------
extern "C" void kernel_launch(void* const* d_in, const int* in_sizes, int n_in,
                              void* d_out, int out_size)
{
    const float* query = (const float*)d_in[0];
    const void*  mask  = d_in[1];
    const float* Wq    = (const float*)d_in[2];
    const float* Wk    = (const float*)d_in[3];
    const float* Wv    = (const float*)d_in[4];
    const float* Wo    = (const float*)d_in[5];
    const float* bo    = (const float*)d_in[6];
    float* out = (float*)d_out;

    float *gq, *gk, *gv, *gctx;
    cudaGetSymbolAddress((void**)&gq,   g_q);
    cudaGetSymbolAddress((void**)&gk,   g_k);
    cudaGetSymbolAddress((void**)&gv,   g_v);
    cudaGetSymbolAddress((void**)&gctx, g_ctx);

    detect_mask_kind_kernel<<<1, 32>>>((const unsigned int*)mask);

    dim3 gemm_grid(DD / 128, MM / 128);
    const float qscale = 0.125f;  // 1/sqrt(dh)
    gemm_nt_kernel<0><<<gemm_grid, 256>>>(query, Wq, nullptr, gq, qscale);
    gemm_nt_kernel<0><<<gemm_grid, 256>>>(query, Wk, nullptr, gk, 1.f);
    gemm_nt_kernel<0><<<gemm_grid, 256>>>(query, Wv, nullptr, gv, 1.f);

    cudaFuncSetAttribute(attn_kernel,
                         cudaFuncAttributeMaxDynamicSharedMemorySize,
                         ATTN_SMEM_BYTES);
    attn_kernel<<<dim3(SS / 64, BB * HH), 256, ATTN_SMEM_BYTES>>>(
        gq, gk, gv, (const uint8_t*)mask, gctx);

    gemm_nt_kernel<1><<<gemm_grid, 256>>>(gctx, Wo, bo, out, 1.f);
}

// round 4
// speedup vs baseline: 1.1631x; 1.1631x over previous
#include <cuda_runtime.h>
#include <stdint.h>

#define BB 2
#define SS 2048
#define DDIM 1024
#define HH 16
#define DH 64
#define MM (BB*SS)

// Scratch (no cudaMalloc allowed). Split-head [B,H,S,dh] layouts.
__device__ float g_qh[(size_t)MM*DDIM];
__device__ float g_ql[(size_t)MM*DDIM];
__device__ float g_kh[(size_t)MM*DDIM];
__device__ float g_kl[(size_t)MM*DDIM];
__device__ float g_v [(size_t)MM*DDIM];
__device__ float g_ctx[(size_t)MM*DDIM];
__device__ int   g_mask_word;   // 1 = 4-byte mask elems, 0 = 1-byte

// ---------------------------------------------------------------- helpers
__device__ __forceinline__ uint32_t f2tf(float x) {
    uint32_t u;
    asm("cvt.rna.tf32.f32 %0, %1;" : "=r"(u) : "f"(x));
    return u;
}
__device__ __forceinline__ void tf_split(float x, uint32_t& hi, uint32_t& lo) {
    hi = f2tf(x);
    lo = f2tf(x - __uint_as_float(hi));
}
__device__ __forceinline__ void mma8(float d[4], const uint32_t a[4],
                                     uint32_t b0, uint32_t b1) {
    asm volatile(
        "mma.sync.aligned.m16n8k8.row.col.f32.tf32.tf32.f32 "
        "{%0,%1,%2,%3},{%4,%5,%6,%7},{%8,%9},{%0,%1,%2,%3};"
        : "+f"(d[0]), "+f"(d[1]), "+f"(d[2]), "+f"(d[3])
        : "r"(a[0]), "r"(a[1]), "r"(a[2]), "r"(a[3]), "r"(b0), "r"(b1));
}
__device__ __forceinline__ void cpa16(void* s, const void* g) {
    uint32_t sa = (uint32_t)__cvta_generic_to_shared(s);
    asm volatile("cp.async.ca.shared.global [%0], [%1], 16;" :: "r"(sa), "l"(g));
}
__device__ __forceinline__ void cpa_commit() { asm volatile("cp.async.commit_group;"); }
__device__ __forceinline__ void cpa_wait0()  { asm volatile("cp.async.wait_group 0;" ::: "memory"); }

// ---------------------------------------------------------------- mask detect
__global__ void detect_mask_kernel(const unsigned* __restrict__ m) {
    if (threadIdx.x == 0) {
        bool word = true;
        #pragma unroll
        for (int i = 0; i < 16; i++) {
            unsigned v = m[i];
            if (v != 0u && v != 1u && v != 0x3f800000u) word = false;
        }
        g_mask_word = word ? 1 : 0;
    }
}

// ---------------------------------------------------------------- GEMM (tf32 TC)
// C = scale * (A @ W^T) [+ bias].  A:[MM,1024], W:[1024,1024] row-major.
// MODE 0: split-head store, hi AND lo tf32 outputs (q,k)
// MODE 1: split-head store, hi tf32 only (v)
// MODE 2: plain [MM,1024] fp32 + bias (out proj)
// 3xtf32 split MMA for full precision. Block 128x128x32, 8 warps (2x4).
#define GST 36   // smem row stride in floats (conflict-free frag reads)

template<int MODE>
__global__ void __launch_bounds__(256) gemm_tc(
    const float* __restrict__ A, const float* __restrict__ W,
    const float* __restrict__ bias, float* __restrict__ Ch,
    float* __restrict__ Cl, float scale)
{
    extern __shared__ float sm[];
    // layout: A0 | B0 | A1 | B1, each 128*GST floats
    float* Abuf[2] = { sm,            sm + 2*128*GST };
    float* Bbuf[2] = { sm + 128*GST,  sm + 3*128*GST };

    const int t = threadIdx.x;
    const int wid = t >> 5, lane = t & 31;
    const int lr = lane >> 2, lc = lane & 3;
    const int m0 = blockIdx.y * 128, n0 = blockIdx.x * 128;
    const int wm = (wid >> 2) * 64, wn = (wid & 3) * 32;

    float acc[4][4][4];
    #pragma unroll
    for (int i = 0; i < 4; i++)
        #pragma unroll
        for (int j = 0; j < 4; j++)
            #pragma unroll
            for (int r = 0; r < 4; r++) acc[i][j][r] = 0.f;

    auto cp_tile = [&](int buf, int k0) {
        #pragma unroll
        for (int i = 0; i < 4; i++) {
            int id = i * 256 + t;            // 0..1023
            int row = id >> 3, kv = (id & 7) * 4;
            cpa16(&Abuf[buf][row * GST + kv], &A[(size_t)(m0 + row) * DDIM + k0 + kv]);
            cpa16(&Bbuf[buf][row * GST + kv], &W[(size_t)(n0 + row) * DDIM + k0 + kv]);
        }
        cpa_commit();
    };

    cp_tile(0, 0);
    for (int c = 0; c < 32; c++) {
        cpa_wait0();
        __syncthreads();
        if (c < 31) cp_tile((c + 1) & 1, (c + 1) * 32);
        const float* Ab = Abuf[c & 1];
        const float* Bb = Bbuf[c & 1];

        #pragma unroll
        for (int ks = 0; ks < 4; ks++) {
            const int k0 = ks * 8;
            uint32_t ah[4][4], al[4][4];
            #pragma unroll
            for (int mi = 0; mi < 4; mi++) {
                int r = wm + mi * 16 + lr;
                tf_split(Ab[(r    ) * GST + k0 + lc    ], ah[mi][0], al[mi][0]);
                tf_split(Ab[(r + 8) * GST + k0 + lc    ], ah[mi][1], al[mi][1]);
                tf_split(Ab[(r    ) * GST + k0 + lc + 4], ah[mi][2], al[mi][2]);
                tf_split(Ab[(r + 8) * GST + k0 + lc + 4], ah[mi][3], al[mi][3]);
            }
            uint32_t bh[4][2], bl[4][2];
            #pragma unroll
            for (int ni = 0; ni < 4; ni++) {
                int n = wn + ni * 8 + lr;
                tf_split(Bb[n * GST + k0 + lc    ], bh[ni][0], bl[ni][0]);
                tf_split(Bb[n * GST + k0 + lc + 4], bh[ni][1], bl[ni][1]);
            }
            #pragma unroll
            for (int mi = 0; mi < 4; mi++)
                #pragma unroll
                for (int ni = 0; ni < 4; ni++) {
                    mma8(acc[mi][ni], ah[mi], bh[ni][0], bh[ni][1]);
                    mma8(acc[mi][ni], al[mi], bh[ni][0], bh[ni][1]);
                    mma8(acc[mi][ni], ah[mi], bl[ni][0], bl[ni][1]);
                }
        }
        __syncthreads();
    }

    // epilogue
    #pragma unroll
    for (int mi = 0; mi < 4; mi++) {
        #pragma unroll
        for (int ni = 0; ni < 4; ni++) {
            int mr0 = m0 + wm + mi * 16 + lr;
            int cl0 = n0 + wn + ni * 8 + 2 * lc;
            #pragma unroll
            for (int rr = 0; rr < 2; rr++) {
                int m = mr0 + rr * 8;
                #pragma unroll
                for (int cc = 0; cc < 2; cc++) {
                    int n = cl0 + cc;
                    float v = acc[mi][ni][rr * 2 + cc] * scale;
                    if (MODE == 2) {
                        Ch[(size_t)m * DDIM + n] = v + bias[n];
                    } else {
                        int b = m >> 11, s = m & (SS - 1);
                        int h = n >> 6, dd = n & (DH - 1);
                        size_t idx = (((size_t)(b * HH + h) * SS + s) * DH) + dd;
                        uint32_t hi = f2tf(v);
                        Ch[idx] = __uint_as_float(hi);
                        if (MODE == 0)
                            Cl[idx] = __uint_as_float(f2tf(v - __uint_as_float(hi)));
                    }
                }
            }
        }
    }
}

// ---------------------------------------------------------------- attention
// Flash attention, tf32 tensor cores. Block = (q-tile 64) x (b*H). 128 threads,
// 4 warps; warp w owns q rows [16w,16w+16). QK^T uses 3xtf32 split (Qh/Ql from
// projection, Kh/Kl likewise); PV is single tf32. K/V double-buffered cp.async.
#define QHS 0
#define QLS (64*68)
#define KH0 (2*64*68)
#define KL0 (3*64*68)
#define KH1 (4*64*68)
#define KL1 (5*64*68)
#define VB0 (6*64*68)
#define VB1 (6*64*68 + 64*72)
#define PBUF (6*64*68 + 2*64*72)
#define MSKF (7*64*68 + 2*64*72)            // float index of mask region
#define ATT_SMEM_BYTES ((7*64*68 + 2*64*72) * 4 + 2*64*64)

__global__ void __launch_bounds__(128) attn_tc(
    const float* __restrict__ QH, const float* __restrict__ QL,
    const float* __restrict__ KH, const float* __restrict__ KL,
    const float* __restrict__ V,  const uint8_t* __restrict__ maskp,
    float* __restrict__ ctx)
{
    extern __shared__ float sm[];
    uint8_t* Mskb = (uint8_t*)(sm + MSKF);

    const int t = threadIdx.x;
    const int wid = t >> 5, lane = t & 31;
    const int lr = lane >> 2, lc = lane & 3;
    const int w16 = wid * 16;
    const int bh = blockIdx.y;
    const int b = bh >> 4, h = bh & 15;
    const int q0 = blockIdx.x * 64;
    const int mword = g_mask_word;
    const unsigned* mask32 = (const unsigned*)maskp;

    const size_t base = (size_t)bh * SS * DH;

    // --- prologue: Q tiles (once) + K/V tile 0 via cp.async
    #pragma unroll
    for (int i = 0; i < 8; i++) {
        int id = i * 128 + t;                // 0..1023
        int row = id >> 4, seg = (id & 15) * 4;
        cpa16(&sm[QHS + row * 68 + seg], &QH[base + (size_t)(q0 + row) * DH + seg]);
        cpa16(&sm[QLS + row * 68 + seg], &QL[base + (size_t)(q0 + row) * DH + seg]);
    }
    auto cp_kv = [&](int buf, int k0) {
        float* kh = sm + (buf ? KH1 : KH0);
        float* kl = sm + (buf ? KL1 : KL0);
        float* vb = sm + (buf ? VB1 : VB0);
        #pragma unroll
        for (int i = 0; i < 8; i++) {
            int id = i * 128 + t;
            int row = id >> 4, seg = (id & 15) * 4;
            size_t g = base + (size_t)(k0 + row) * DH + seg;
            cpa16(&kh[row * 68 + seg], &KH[g]);
            cpa16(&kl[row * 68 + seg], &KL[g]);
            cpa16(&vb[row * 72 + seg], &V[g]);
        }
        cpa_commit();
    };
    cp_kv(0, 0);

    // mask tile 0 -> regs -> smem buf 0
    uint32_t mr[8];
    auto ld_mask = [&](int k0) {
        if (mword) {
            #pragma unroll
            for (int i = 0; i < 8; i++) {
                int id = i * 128 + t;
                int row = id >> 4, seg = id & 15;
                const unsigned* p = mask32 + ((size_t)(b * SS + q0 + row)) * SS + k0 + seg * 4;
                uint4 u = *(const uint4*)p;
                mr[i] = (u.x != 0 ? 1u : 0) | (u.y != 0 ? 0x100u : 0)
                      | (u.z != 0 ? 0x10000u : 0) | (u.w != 0 ? 0x1000000u : 0);
            }
        } else {
            #pragma unroll
            for (int i = 0; i < 2; i++) {
                int id = i * 128 + t;
                int row = id >> 2, seg = id & 3;
                const uint8_t* p = maskp + ((size_t)(b * SS + q0 + row)) * SS + k0 + seg * 16;
                uint4 u = *(const uint4*)p;
                mr[i * 4 + 0] = u.x; mr[i * 4 + 1] = u.y;
                mr[i * 4 + 2] = u.z; mr[i * 4 + 3] = u.w;
            }
        }
    };
    auto st_mask = [&](int buf) {
        uint32_t* Mw = (uint32_t*)(Mskb + buf * 4096);
        if (mword) {
            #pragma unroll
            for (int i = 0; i < 8; i++) {
                int id = i * 128 + t;
                int row = id >> 4, seg = id & 15;
                Mw[row * 16 + seg] = mr[i];
            }
        } else {
            #pragma unroll
            for (int i = 0; i < 2; i++) {
                int id = i * 128 + t;
                int row = id >> 2, seg = id & 3;
                #pragma unroll
                for (int j = 0; j < 4; j++) Mw[row * 16 + seg * 4 + j] = mr[i * 4 + j];
            }
        }
    };
    ld_mask(0);
    st_mask(0);

    float m_a = -1e30f, m_b = -1e30f, l_a = 0.f, l_b = 0.f;
    float o[8][4];
    #pragma unroll
    for (int nf = 0; nf < 8; nf++)
        #pragma unroll
        for (int r = 0; r < 4; r++) o[nf][r] = 0.f;

    for (int c = 0; c < SS / 64; c++) {
        cpa_wait0();
        __syncthreads();
        const int buf = c & 1;
        if (c + 1 < SS / 64) {
            cp_kv(buf ^ 1, (c + 1) * 64);
            ld_mask((c + 1) * 64);      // lands in regs during compute
        }
        const float* khp = sm + (buf ? KH1 : KH0);
        const float* klp = sm + (buf ? KL1 : KL0);
        const float* vbp = sm + (buf ? VB1 : VB0);
        const uint8_t* Mb = Mskb + buf * 4096;

        // ---- scores S = Q K^T (split 3xtf32)
        float s[8][4];
        #pragma unroll
        for (int nf = 0; nf < 8; nf++)
            #pragma unroll
            for (int r = 0; r < 4; r++) s[nf][r] = 0.f;
        #pragma unroll
        for (int ks = 0; ks < 8; ks++) {
            const int k0 = ks * 8;
            uint32_t qh[4], ql[4];
            qh[0] = __float_as_uint(sm[QHS + (w16 + lr    ) * 68 + k0 + lc    ]);
            qh[1] = __float_as_uint(sm[QHS + (w16 + lr + 8) * 68 + k0 + lc    ]);
            qh[2] = __float_as_uint(sm[QHS + (w16 + lr    ) * 68 + k0 + lc + 4]);
            qh[3] = __float_as_uint(sm[QHS + (w16 + lr + 8) * 68 + k0 + lc + 4]);
            ql[0] = __float_as_uint(sm[QLS + (w16 + lr    ) * 68 + k0 + lc    ]);
            ql[1] = __float_as_uint(sm[QLS + (w16 + lr + 8) * 68 + k0 + lc    ]);
            ql[2] = __float_as_uint(sm[QLS + (w16 + lr    ) * 68 + k0 + lc + 4]);
            ql[3] = __float_as_uint(sm[QLS + (w16 + lr + 8) * 68 + k0 + lc + 4]);
            #pragma unroll
            for (int nf = 0; nf < 8; nf++) {
                uint32_t kh0 = __float_as_uint(khp[(nf * 8 + lr) * 68 + k0 + lc    ]);
                uint32_t kh1 = __float_as_uint(khp[(nf * 8 + lr) * 68 + k0 + lc + 4]);
                uint32_t kl0 = __float_as_uint(klp[(nf * 8 + lr) * 68 + k0 + lc    ]);
                uint32_t kl1 = __float_as_uint(klp[(nf * 8 + lr) * 68 + k0 + lc + 4]);
                mma8(s[nf], qh, kh0, kh1);
                mma8(s[nf], ql, kh0, kh1);
                mma8(s[nf], qh, kl0, kl1);
            }
        }

        // ---- mask + online softmax
        const int ra = w16 + lr, rb = ra + 8;
        float mxa = -1e30f, mxb = -1e30f;
        #pragma unroll
        for (int nf = 0; nf < 8; nf++) {
            int c0 = nf * 8 + 2 * lc;
            if (Mb[ra * 64 + c0    ]) s[nf][0] = -1e30f;
            if (Mb[ra * 64 + c0 + 1]) s[nf][1] = -1e30f;
            if (Mb[rb * 64 + c0    ]) s[nf][2] = -1e30f;
            if (Mb[rb * 64 + c0 + 1]) s[nf][3] = -1e30f;
            mxa = fmaxf(mxa, fmaxf(s[nf][0], s[nf][1]));
            mxb = fmaxf(mxb, fmaxf(s[nf][2], s[nf][3]));
        }
        mxa = fmaxf(mxa, __shfl_xor_sync(0xFFFFFFFFu, mxa, 1));
        mxa = fmaxf(mxa, __shfl_xor_sync(0xFFFFFFFFu, mxa, 2));
        mxb = fmaxf(mxb, __shfl_xor_sync(0xFFFFFFFFu, mxb, 1));
        mxb = fmaxf(mxb, __shfl_xor_sync(0xFFFFFFFFu, mxb, 2));
        float mna = fmaxf(m_a, mxa), mnb = fmaxf(m_b, mxb);
        float ca = __expf(m_a - mna), cb = __expf(m_b - mnb);
        float sa = 0.f, sb = 0.f;
        #pragma unroll
        for (int nf = 0; nf < 8; nf++) {
            int c0 = nf * 8 + 2 * lc;
            float p0 = (s[nf][0] <= -1e29f) ? 0.f : __expf(s[nf][0] - mna);
            float p1 = (s[nf][1] <= -1e29f) ? 0.f : __expf(s[nf][1] - mna);
            float p2 = (s[nf][2] <= -1e29f) ? 0.f : __expf(s[nf][2] - mnb);
            float p3 = (s[nf][3] <= -1e29f) ? 0.f : __expf(s[nf][3] - mnb);
            sa += p0 + p1; sb += p2 + p3;
            sm[PBUF + ra * 68 + c0    ] = __uint_as_float(f2tf(p0));
            sm[PBUF + ra * 68 + c0 + 1] = __uint_as_float(f2tf(p1));
            sm[PBUF + rb * 68 + c0    ] = __uint_as_float(f2tf(p2));
            sm[PBUF + rb * 68 + c0 + 1] = __uint_as_float(f2tf(p3));
        }
        sa += __shfl_xor_sync(0xFFFFFFFFu, sa, 1);
        sa += __shfl_xor_sync(0xFFFFFFFFu, sa, 2);
        sb += __shfl_xor_sync(0xFFFFFFFFu, sb, 1);
        sb += __shfl_xor_sync(0xFFFFFFFFu, sb, 2);
        l_a = l_a * ca + sa; l_b = l_b * cb + sb;
        m_a = mna; m_b = mnb;
        #pragma unroll
        for (int nf = 0; nf < 8; nf++) {
            o[nf][0] *= ca; o[nf][1] *= ca; o[nf][2] *= cb; o[nf][3] *= cb;
        }
        __syncthreads();   // P visible to all warps

        // ---- O += P V (single tf32; V already tf32-rounded)
        #pragma unroll
        for (int ks = 0; ks < 8; ks++) {
            const int k0 = ks * 8;
            uint32_t pa[4];
            pa[0] = __float_as_uint(sm[PBUF + (w16 + lr    ) * 68 + k0 + lc    ]);
            pa[1] = __float_as_uint(sm[PBUF + (w16 + lr + 8) * 68 + k0 + lc    ]);
            pa[2] = __float_as_uint(sm[PBUF + (w16 + lr    ) * 68 + k0 + lc + 4]);
            pa[3] = __float_as_uint(sm[PBUF + (w16 + lr + 8) * 68 + k0 + lc + 4]);
            #pragma unroll
            for (int nf = 0; nf < 8; nf++) {
                uint32_t v0 = __float_as_uint(vbp[(k0 + lc    ) * 72 + nf * 8 + lr]);
                uint32_t v1 = __float_as_uint(vbp[(k0 + lc + 4) * 72 + nf * 8 + lr]);
                mma8(o[nf], pa, v0, v1);
            }
        }

        if (c + 1 < SS / 64) st_mask(buf ^ 1);
    }

    // ---- epilogue: normalize, write combined-head ctx
    float inva = (l_a > 0.f) ? (1.f / l_a) : 0.f;
    float invb = (l_b > 0.f) ? (1.f / l_b) : 0.f;
    const int qa = q0 + w16 + lr, qb = qa + 8;
    #pragma unroll
    for (int nf = 0; nf < 8; nf++) {
        int dd = h * DH + nf * 8 + 2 * lc;
        float2 va = { o[nf][0] * inva, o[nf][1] * inva };
        float2 vb = { o[nf][2] * invb, o[nf][3] * invb };
        *(float2*)&ctx[(size_t)(b * SS + qa) * DDIM + dd] = va;
        *(float2*)&ctx[(size_t)(b * SS + qb) * DDIM + dd] = vb;
    }
}

// ---------------------------------------------------------------- launcher
#define GEMM_SMEM (4 * 128 * GST * 4)

extern "C" void kernel_launch(void* const* d_in, const int* in_sizes, int n_in,
                              void* d_out, int out_size)
{
    const float* query = (const float*)d_in[0];
    const void*  mask  = d_in[1];
    const float* Wq    = (const float*)d_in[2];
    const float* Wk    = (const float*)d_in[3];
    const float* Wv    = (const float*)d_in[4];
    const float* Wo    = (const float*)d_in[5];
    const float* bo    = (const float*)d_in[6];
    float* out = (float*)d_out;

    float *gqh, *gql, *gkh, *gkl, *gv, *gctx;
    cudaGetSymbolAddress((void**)&gqh, g_qh);
    cudaGetSymbolAddress((void**)&gql, g_ql);
    cudaGetSymbolAddress((void**)&gkh, g_kh);
    cudaGetSymbolAddress((void**)&gkl, g_kl);
    cudaGetSymbolAddress((void**)&gv,  g_v);
    cudaGetSymbolAddress((void**)&gctx, g_ctx);

    cudaFuncSetAttribute(gemm_tc<0>, cudaFuncAttributeMaxDynamicSharedMemorySize, GEMM_SMEM);
    cudaFuncSetAttribute(gemm_tc<1>, cudaFuncAttributeMaxDynamicSharedMemorySize, GEMM_SMEM);
    cudaFuncSetAttribute(gemm_tc<2>, cudaFuncAttributeMaxDynamicSharedMemorySize, GEMM_SMEM);
    cudaFuncSetAttribute(attn_tc, cudaFuncAttributeMaxDynamicSharedMemorySize, ATT_SMEM_BYTES);

    detect_mask_kernel<<<1, 32>>>((const unsigned*)mask);

    dim3 gg(DDIM / 128, MM / 128);
    gemm_tc<0><<<gg, 256, GEMM_SMEM>>>(query, Wq, nullptr, gqh, gql, 0.125f);
    gemm_tc<0><<<gg, 256, GEMM_SMEM>>>(query, Wk, nullptr, gkh, gkl, 1.f);
    gemm_tc<1><<<gg, 256, GEMM_SMEM>>>(query, Wv, nullptr, gv, nullptr, 1.f);

    attn_tc<<<dim3(SS / 64, BB * HH), 128, ATT_SMEM_BYTES>>>(
        gqh, gql, gkh, gkl, gv, (const uint8_t*)mask, gctx);

    gemm_tc<2><<<gg, 256, GEMM_SMEM>>>(gctx, Wo, bo, out, nullptr, 1.f);
}

// round 9
// speedup vs baseline: 2.1523x; 1.8506x over previous
#include <cuda_runtime.h>
#include <cuda_bf16.h>
#include <stdint.h>

#define BB 2
#define SS 2048
#define DDIM 1024
#define HH 16
#define DH 64
#define MM (BB*SS)

typedef __nv_bfloat16 bf16;

// -------- global scratch (no cudaMalloc allowed) --------
__device__ bf16 g_xh[(size_t)MM*DDIM],  g_xl[(size_t)MM*DDIM];     // query split
__device__ bf16 g_wqh[(size_t)DDIM*DDIM], g_wql[(size_t)DDIM*DDIM];
__device__ bf16 g_wkh[(size_t)DDIM*DDIM], g_wkl[(size_t)DDIM*DDIM];
__device__ bf16 g_wvh[(size_t)DDIM*DDIM], g_wvl[(size_t)DDIM*DDIM];
__device__ bf16 g_woh[(size_t)DDIM*DDIM], g_wol[(size_t)DDIM*DDIM];
__device__ bf16 g_qh[(size_t)MM*DDIM],  g_ql[(size_t)MM*DDIM];     // [B,H,S,dh]
__device__ bf16 g_kh[(size_t)MM*DDIM],  g_kl[(size_t)MM*DDIM];     // [B,H,S,dh]
__device__ bf16 g_vh[(size_t)MM*DDIM],  g_vl[(size_t)MM*DDIM];     // [B,H,dh,S] (transposed)
__device__ bf16 g_ch[(size_t)MM*DDIM],  g_cl[(size_t)MM*DDIM];     // ctx [B,S,D]
__device__ int  g_mask_word;

// -------- helpers --------
__device__ __forceinline__ void bsplit(float x, bf16& h, bf16& l) {
    h = __float2bfloat16_rn(x);
    l = __float2bfloat16_rn(x - __bfloat162float(h));
}
__device__ __forceinline__ uint32_t lds32(const bf16* p) { return *(const uint32_t*)p; }
__device__ __forceinline__ void mma16(float d[4], const uint32_t a[4],
                                      uint32_t b0, uint32_t b1) {
    asm volatile(
        "mma.sync.aligned.m16n8k16.row.col.f32.bf16.bf16.f32 "
        "{%0,%1,%2,%3},{%4,%5,%6,%7},{%8,%9},{%0,%1,%2,%3};"
        : "+f"(d[0]), "+f"(d[1]), "+f"(d[2]), "+f"(d[3])
        : "r"(a[0]), "r"(a[1]), "r"(a[2]), "r"(a[3]), "r"(b0), "r"(b1));
}
__device__ __forceinline__ void cpa16(void* s, const void* g) {
    uint32_t sa = (uint32_t)__cvta_generic_to_shared(s);
    asm volatile("cp.async.ca.shared.global [%0], [%1], 16;" :: "r"(sa), "l"(g));
}
__device__ __forceinline__ void cpa_commit() { asm volatile("cp.async.commit_group;"); }
__device__ __forceinline__ void cpa_wait0()  { asm volatile("cp.async.wait_group 0;" ::: "memory"); }

// -------- mask dtype detect --------
__global__ void detect_mask_kernel(const unsigned* __restrict__ m) {
    if (threadIdx.x == 0) {
        bool word = true;
        #pragma unroll
        for (int i = 0; i < 16; i++) {
            unsigned v = m[i];
            if (v != 0u && v != 1u && v != 0x3f800000u) word = false;
        }
        g_mask_word = word ? 1 : 0;
    }
}

// -------- fp32 -> bf16 hi/lo split (elementwise) --------
__global__ void __launch_bounds__(256) split_f32(
    const float* __restrict__ x, bf16* __restrict__ h, bf16* __restrict__ l, int n)
{
    int i = (blockIdx.x * 256 + threadIdx.x) * 2;
    if (i < n) {
        float2 v = *(const float2*)(x + i);
        bf16 h0, l0, h1, l1;
        bsplit(v.x, h0, l0);
        bsplit(v.y, h1, l1);
        *(__nv_bfloat162*)(h + i) = __nv_bfloat162(h0, h1);
        *(__nv_bfloat162*)(l + i) = __nv_bfloat162(l0, l1);
    }
}

// ---------------------------------------------------------------- GEMM bf16x3
// C = scale * (A @ W^T) [+bias].  A: hi/lo bf16 [MM,1024], W: hi/lo [1024,1024].
// MODE 0: split-head [B,H,S,dh] hi+lo out (q,k)
// MODE 1: transposed split-head [B,H,dh,S] hi+lo out (v)
// MODE 2: fp32 [MM,1024] + bias (output proj)
// Block 128x128x32, 8 warps (2x4), warp tile 64x32, double-buffered cp.async.
#define GS 40                 // smem row stride in bf16 (80B: conflict-free)
#define TSZ (128*GS)          // one sub-array
#define GEMM_SMEM (2*4*TSZ*2) // bytes: 2 bufs x {Ah,Al,Bh,Bl}

template<int MODE>
__global__ void __launch_bounds__(256, 2) gemm_bf3(
    const bf16* __restrict__ Agh, const bf16* __restrict__ Agl,
    const bf16* __restrict__ Wgh, const bf16* __restrict__ Wgl,
    const float* __restrict__ bias, bf16* __restrict__ Ch,
    bf16* __restrict__ Cl, float* __restrict__ Co, float scale)
{
    extern __shared__ bf16 smb[];
    const int t = threadIdx.x;
    const int wid = t >> 5, lane = t & 31;
    const int lr = lane >> 2, lc = lane & 3;
    const int m0 = blockIdx.y * 128, n0 = blockIdx.x * 128;
    const int wm = (wid >> 2) * 64, wn = (wid & 3) * 32;

    float acc[4][4][4];
    #pragma unroll
    for (int i = 0; i < 4; i++)
        #pragma unroll
        for (int j = 0; j < 4; j++)
            #pragma unroll
            for (int r = 0; r < 4; r++) acc[i][j][r] = 0.f;

    auto cp_tile = [&](int buf, int k0) {
        bf16* base = smb + buf * 4 * TSZ;
        #pragma unroll
        for (int i = 0; i < 8; i++) {
            const int sub = i >> 1;
            const int j = (i & 1) * 256 + t;     // 0..511
            const int row = j >> 2, ch = (j & 3) * 8;
            const bf16* src;
            if (sub == 0)      src = Agh + (size_t)(m0 + row) * DDIM + k0 + ch;
            else if (sub == 1) src = Agl + (size_t)(m0 + row) * DDIM + k0 + ch;
            else if (sub == 2) src = Wgh + (size_t)(n0 + row) * DDIM + k0 + ch;
            else               src = Wgl + (size_t)(n0 + row) * DDIM + k0 + ch;
            cpa16(&base[sub * TSZ + row * GS + ch], src);
        }
        cpa_commit();
    };

    cp_tile(0, 0);
    for (int c = 0; c < 32; c++) {
        cpa_wait0();
        __syncthreads();
        if (c < 31) cp_tile((c + 1) & 1, (c + 1) * 32);
        const bf16* Ahs = smb + (c & 1) * 4 * TSZ;
        const bf16* Als = Ahs + TSZ;
        const bf16* Bhs = Ahs + 2 * TSZ;
        const bf16* Bls = Ahs + 3 * TSZ;

        #pragma unroll
        for (int ks = 0; ks < 2; ks++) {
            const int kc = ks * 16 + 2 * lc;
            uint32_t ah[4][4], al[4][4];
            #pragma unroll
            for (int mi = 0; mi < 4; mi++) {
                const int r = wm + mi * 16 + lr;
                ah[mi][0] = lds32(Ahs + (r    ) * GS + kc);
                ah[mi][1] = lds32(Ahs + (r + 8) * GS + kc);
                ah[mi][2] = lds32(Ahs + (r    ) * GS + kc + 8);
                ah[mi][3] = lds32(Ahs + (r + 8) * GS + kc + 8);
                al[mi][0] = lds32(Als + (r    ) * GS + kc);
                al[mi][1] = lds32(Als + (r + 8) * GS + kc);
                al[mi][2] = lds32(Als + (r    ) * GS + kc + 8);
                al[mi][3] = lds32(Als + (r + 8) * GS + kc + 8);
            }
            uint32_t bh[4][2], bl[4][2];
            #pragma unroll
            for (int ni = 0; ni < 4; ni++) {
                const int n = wn + ni * 8 + lr;
                bh[ni][0] = lds32(Bhs + n * GS + kc);
                bh[ni][1] = lds32(Bhs + n * GS + kc + 8);
                bl[ni][0] = lds32(Bls + n * GS + kc);
                bl[ni][1] = lds32(Bls + n * GS + kc + 8);
            }
            #pragma unroll
            for (int mi = 0; mi < 4; mi++)
                #pragma unroll
                for (int ni = 0; ni < 4; ni++) {
                    mma16(acc[mi][ni], ah[mi], bh[ni][0], bh[ni][1]);
                    mma16(acc[mi][ni], ah[mi], bl[ni][0], bl[ni][1]);
                    mma16(acc[mi][ni], al[mi], bh[ni][0], bh[ni][1]);
                }
        }
        __syncthreads();
    }

    // epilogue
    #pragma unroll
    for (int mi = 0; mi < 4; mi++) {
        #pragma unroll
        for (int ni = 0; ni < 4; ni++) {
            const int n = n0 + wn + ni * 8 + 2 * lc;   // even; pair n, n+1
            #pragma unroll
            for (int rr = 0; rr < 2; rr++) {
                const int m = m0 + wm + mi * 16 + lr + rr * 8;
                float v0 = acc[mi][ni][rr * 2 + 0] * scale;
                float v1 = acc[mi][ni][rr * 2 + 1] * scale;
                if (MODE == 2) {
                    Co[(size_t)m * DDIM + n]     = v0 + bias[n];
                    Co[(size_t)m * DDIM + n + 1] = v1 + bias[n + 1];
                } else {
                    const int b = m >> 11, s = m & (SS - 1);
                    const int h = n >> 6,  dd = n & (DH - 1);
                    bf16 h0, l0, h1, l1;
                    bsplit(v0, h0, l0);
                    bsplit(v1, h1, l1);
                    if (MODE == 0) {
                        size_t idx = (((size_t)(b * HH + h) * SS + s) * DH) + dd;
                        *(__nv_bfloat162*)&Ch[idx] = __nv_bfloat162(h0, h1);
                        *(__nv_bfloat162*)&Cl[idx] = __nv_bfloat162(l0, l1);
                    } else {  // MODE 1: transposed [B,H,dh,S]
                        size_t idx = (((size_t)(b * HH + h) * DH + dd) * SS) + s;
                        Ch[idx] = h0; Cl[idx] = l0;
                        Ch[idx + SS] = h1; Cl[idx + SS] = l1;
                    }
                }
            }
        }
    }
}

// ---------------------------------------------------------------- attention
// bf16x3 flash attention. Block: 128 q-rows x one (b,h). 256 threads, 8 warps;
// warp w owns q rows [16w,16w+16). K/V 64-key tiles double-buffered cp.async.
// smem bf16-elem offsets (stride 72 rows = 144B, conflict-free):
#define AQH 0
#define AQL (128*72)
#define AKH(b) (2*128*72 + (b)*2*64*72)
#define AKL(b) (AKH(b) + 64*72)
#define AVH(b) (2*128*72 + 4*64*72 + (b)*2*64*72)
#define AVL(b) (AVH(b) + 64*72)
#define APH (2*128*72 + 8*64*72)
#define APL (APH + 128*72)
#define AMSK_BYTE ((APL + 128*72) * 2)
#define ATT_SMEM_BYTES (AMSK_BYTE + 2*128*64)

__global__ void __launch_bounds__(256) attn_bf3(
    const bf16* __restrict__ QH, const bf16* __restrict__ QL,
    const bf16* __restrict__ KH, const bf16* __restrict__ KL,
    const bf16* __restrict__ VH, const bf16* __restrict__ VL,
    const uint8_t* __restrict__ maskp,
    bf16* __restrict__ CH, bf16* __restrict__ CL)
{
    extern __shared__ bf16 smb[];
    uint8_t* Mskb = (uint8_t*)smb + AMSK_BYTE;

    const int t = threadIdx.x;
    const int wid = t >> 5, lane = t & 31;
    const int lr = lane >> 2, lc = lane & 3;
    const int w16 = wid * 16;
    const int bh = blockIdx.y;
    const int b = bh >> 4, h = bh & 15;
    const int q0 = blockIdx.x * 128;
    const int mword = g_mask_word;
    const unsigned* mask32 = (const unsigned*)maskp;

    const size_t base = (size_t)bh * SS * DH;   // Q,K: [bh][s][dh] ; V: [bh][dh][s]

    // Q tiles (persistent)
    #pragma unroll
    for (int i = 0; i < 8; i++) {
        const int arr = i >> 2;
        const int j = (i & 3) * 256 + t;       // 0..1023
        const int row = j >> 3, ch = (j & 7) * 8;
        const bf16* src = (arr ? QL : QH) + base + (size_t)(q0 + row) * DH + ch;
        cpa16(&smb[(arr ? AQL : AQH) + row * 72 + ch], src);
    }
    auto cp_kv = [&](int buf, int k0) {
        #pragma unroll
        for (int i = 0; i < 8; i++) {
            const int sub = i >> 1;
            const int j = (i & 1) * 256 + t;   // 0..511
            const int row = j >> 3, ch = (j & 7) * 8;
            const bf16* src;
            int doff;
            if (sub == 0)      { src = KH + base + (size_t)(k0 + row) * DH + ch; doff = AKH(buf); }
            else if (sub == 1) { src = KL + base + (size_t)(k0 + row) * DH + ch; doff = AKL(buf); }
            else if (sub == 2) { src = VH + base + (size_t)row * SS + k0 + ch;   doff = AVH(buf); }
            else               { src = VL + base + (size_t)row * SS + k0 + ch;   doff = AVL(buf); }
            cpa16(&smb[doff + row * 72 + ch], src);
        }
        cpa_commit();
    };
    cp_kv(0, 0);

    uint32_t mr[8];
    auto ld_mask = [&](int k0) {
        if (mword) {
            #pragma unroll
            for (int i = 0; i < 8; i++) {
                const int id = i * 256 + t;
                const int row = id >> 4, seg = id & 15;
                const unsigned* p = mask32 + ((size_t)(b * SS + q0 + row)) * SS + k0 + seg * 4;
                uint4 u = *(const uint4*)p;
                mr[i] = (u.x ? 1u : 0) | (u.y ? 0x100u : 0)
                      | (u.z ? 0x10000u : 0) | (u.w ? 0x1000000u : 0);
            }
        } else {
            #pragma unroll
            for (int i = 0; i < 2; i++) {
                const int id = i * 256 + t;
                const int row = id >> 2, seg = id & 3;
                const uint8_t* p = maskp + ((size_t)(b * SS + q0 + row)) * SS + k0 + seg * 16;
                uint4 u = *(const uint4*)p;
                mr[i * 4 + 0] = u.x; mr[i * 4 + 1] = u.y;
                mr[i * 4 + 2] = u.z; mr[i * 4 + 3] = u.w;
            }
        }
    };
    auto st_mask = [&](int buf) {
        uint32_t* Mw = (uint32_t*)(Mskb + buf * 8192);
        if (mword) {
            #pragma unroll
            for (int i = 0; i < 8; i++) {
                const int id = i * 256 + t;
                Mw[(id >> 4) * 16 + (id & 15)] = mr[i];
            }
        } else {
            #pragma unroll
            for (int i = 0; i < 2; i++) {
                const int id = i * 256 + t;
                const int row = id >> 2, seg = id & 3;
                #pragma unroll
                for (int j = 0; j < 4; j++) Mw[row * 16 + seg * 4 + j] = mr[i * 4 + j];
            }
        }
    };
    ld_mask(0);
    st_mask(0);

    float m_a = -1e30f, m_b = -1e30f, l_a = 0.f, l_b = 0.f;
    float o[8][4];
    #pragma unroll
    for (int nf = 0; nf < 8; nf++)
        #pragma unroll
        for (int r = 0; r < 4; r++) o[nf][r] = 0.f;

    for (int c = 0; c < SS / 64; c++) {
        cpa_wait0();
        __syncthreads();
        const int buf = c & 1;
        if (c + 1 < SS / 64) {
            cp_kv(buf ^ 1, (c + 1) * 64);
            ld_mask((c + 1) * 64);
        }
        const bf16* khp = smb + AKH(buf);
        const bf16* klp = smb + AKL(buf);
        const bf16* vhp = smb + AVH(buf);
        const bf16* vlp = smb + AVL(buf);
        const uint8_t* Mb = Mskb + buf * 8192;

        // ---- S = Q K^T  (QhKh + QhKl + QlKh)
        float s[8][4];
        #pragma unroll
        for (int nf = 0; nf < 8; nf++)
            #pragma unroll
            for (int r = 0; r < 4; r++) s[nf][r] = 0.f;
        #pragma unroll
        for (int ks = 0; ks < 4; ks++) {
            const int kc = ks * 16 + 2 * lc;
            const int r = w16 + lr;
            uint32_t qh[4], ql[4];
            qh[0] = lds32(smb + AQH + (r    ) * 72 + kc);
            qh[1] = lds32(smb + AQH + (r + 8) * 72 + kc);
            qh[2] = lds32(smb + AQH + (r    ) * 72 + kc + 8);
            qh[3] = lds32(smb + AQH + (r + 8) * 72 + kc + 8);
            ql[0] = lds32(smb + AQL + (r    ) * 72 + kc);
            ql[1] = lds32(smb + AQL + (r + 8) * 72 + kc);
            ql[2] = lds32(smb + AQL + (r    ) * 72 + kc + 8);
            ql[3] = lds32(smb + AQL + (r + 8) * 72 + kc + 8);
            #pragma unroll
            for (int nf = 0; nf < 8; nf++) {
                const int n = nf * 8 + lr;
                uint32_t kh0 = lds32(khp + n * 72 + kc);
                uint32_t kh1 = lds32(khp + n * 72 + kc + 8);
                uint32_t kl0 = lds32(klp + n * 72 + kc);
                uint32_t kl1 = lds32(klp + n * 72 + kc + 8);
                mma16(s[nf], qh, kh0, kh1);
                mma16(s[nf], qh, kl0, kl1);
                mma16(s[nf], ql, kh0, kh1);
            }
        }

        // ---- mask + online softmax
        const int ra = w16 + lr, rb = ra + 8;
        float mxa = -1e30f, mxb = -1e30f;
        #pragma unroll
        for (int nf = 0; nf < 8; nf++) {
            const int c0 = nf * 8 + 2 * lc;
            if (Mb[ra * 64 + c0    ]) s[nf][0] = -1e30f;
            if (Mb[ra * 64 + c0 + 1]) s[nf][1] = -1e30f;
            if (Mb[rb * 64 + c0    ]) s[nf][2] = -1e30f;
            if (Mb[rb * 64 + c0 + 1]) s[nf][3] = -1e30f;
            mxa = fmaxf(mxa, fmaxf(s[nf][0], s[nf][1]));
            mxb = fmaxf(mxb, fmaxf(s[nf][2], s[nf][3]));
        }
        mxa = fmaxf(mxa, __shfl_xor_sync(0xFFFFFFFFu, mxa, 1));
        mxa = fmaxf(mxa, __shfl_xor_sync(0xFFFFFFFFu, mxa, 2));
        mxb = fmaxf(mxb, __shfl_xor_sync(0xFFFFFFFFu, mxb, 1));
        mxb = fmaxf(mxb, __shfl_xor_sync(0xFFFFFFFFu, mxb, 2));
        float mna = fmaxf(m_a, mxa), mnb = fmaxf(m_b, mxb);
        float ca = __expf(m_a - mna), cb = __expf(m_b - mnb);
        float sa = 0.f, sb = 0.f;
        #pragma unroll
        for (int nf = 0; nf < 8; nf++) {
            const int c0 = nf * 8 + 2 * lc;
            float p0 = (s[nf][0] <= -1e29f) ? 0.f : __expf(s[nf][0] - mna);
            float p1 = (s[nf][1] <= -1e29f) ? 0.f : __expf(s[nf][1] - mna);
            float p2 = (s[nf][2] <= -1e29f) ? 0.f : __expf(s[nf][2] - mnb);
            float p3 = (s[nf][3] <= -1e29f) ? 0.f : __expf(s[nf][3] - mnb);
            sa += p0 + p1; sb += p2 + p3;
            bf16 h0, l0, h1, l1;
            bsplit(p0, h0, l0); bsplit(p1, h1, l1);
            *(__nv_bfloat162*)&smb[APH + ra * 72 + c0] = __nv_bfloat162(h0, h1);
            *(__nv_bfloat162*)&smb[APL + ra * 72 + c0] = __nv_bfloat162(l0, l1);
            bsplit(p2, h0, l0); bsplit(p3, h1, l1);
            *(__nv_bfloat162*)&smb[APH + rb * 72 + c0] = __nv_bfloat162(h0, h1);
            *(__nv_bfloat162*)&smb[APL + rb * 72 + c0] = __nv_bfloat162(l0, l1);
        }
        sa += __shfl_xor_sync(0xFFFFFFFFu, sa, 1);
        sa += __shfl_xor_sync(0xFFFFFFFFu, sa, 2);
        sb += __shfl_xor_sync(0xFFFFFFFFu, sb, 1);
        sb += __shfl_xor_sync(0xFFFFFFFFu, sb, 2);
        l_a = l_a * ca + sa; l_b = l_b * cb + sb;
        m_a = mna; m_b = mnb;
        #pragma unroll
        for (int nf = 0; nf < 8; nf++) {
            o[nf][0] *= ca; o[nf][1] *= ca; o[nf][2] *= cb; o[nf][3] *= cb;
        }
        __syncwarp();  // each warp consumes only its own P rows

        // ---- O += P V  (PhVh + PhVl + PlVh); V tile is [dh][key] (k-contig)
        #pragma unroll
        for (int ks = 0; ks < 4; ks++) {
            const int kc = ks * 16 + 2 * lc;
            const int r = w16 + lr;
            uint32_t ph[4], pl[4];
            ph[0] = lds32(smb + APH + (r    ) * 72 + kc);
            ph[1] = lds32(smb + APH + (r + 8) * 72 + kc);
            ph[2] = lds32(smb + APH + (r    ) * 72 + kc + 8);
            ph[3] = lds32(smb + APH + (r + 8) * 72 + kc + 8);
            pl[0] = lds32(smb + APL + (r    ) * 72 + kc);
            pl[1] = lds32(smb + APL + (r + 8) * 72 + kc);
            pl[2] = lds32(smb + APL + (r    ) * 72 + kc + 8);
            pl[3] = lds32(smb + APL + (r + 8) * 72 + kc + 8);
            #pragma unroll
            for (int nf = 0; nf < 8; nf++) {
                const int n = nf * 8 + lr;
                uint32_t vh0 = lds32(vhp + n * 72 + kc);
                uint32_t vh1 = lds32(vhp + n * 72 + kc + 8);
                uint32_t vl0 = lds32(vlp + n * 72 + kc);
                uint32_t vl1 = lds32(vlp + n * 72 + kc + 8);
                mma16(o[nf], ph, vh0, vh1);
                mma16(o[nf], ph, vl0, vl1);
                mma16(o[nf], pl, vh0, vh1);
            }
        }

        if (c + 1 < SS / 64) st_mask(buf ^ 1);
    }

    // ---- epilogue: normalize, split, write ctx hi/lo [B,S,D]
    const float inva = (l_a > 0.f) ? (1.f / l_a) : 0.f;
    const float invb = (l_b > 0.f) ? (1.f / l_b) : 0.f;
    const int qa = q0 + w16 + lr, qb = qa + 8;
    #pragma unroll
    for (int nf = 0; nf < 8; nf++) {
        const int dd = h * DH + nf * 8 + 2 * lc;
        bf16 h0, l0, h1, l1;
        bsplit(o[nf][0] * inva, h0, l0); bsplit(o[nf][1] * inva, h1, l1);
        size_t ia = (size_t)(b * SS + qa) * DDIM + dd;
        *(__nv_bfloat162*)&CH[ia] = __nv_bfloat162(h0, h1);
        *(__nv_bfloat162*)&CL[ia] = __nv_bfloat162(l0, l1);
        bsplit(o[nf][2] * invb, h0, l0); bsplit(o[nf][3] * invb, h1, l1);
        size_t ib = (size_t)(b * SS + qb) * DDIM + dd;
        *(__nv_bfloat162*)&CH[ib] = __nv_bfloat162(h0, h1);
        *(__nv_bfloat162*)&CL[ib] = __nv_bfloat162(l0, l1);
    }
}

// ---------------------------------------------------------------- launcher
extern "C" void kernel_launch(void* const* d_in, const int* in_sizes, int n_in,
                              void* d_out, int out_size)
{
    const float* query = (const float*)d_in[0];
    const void*  mask  = d_in[1];
    const float* Wq    = (const float*)d_in[2];
    const float* Wk    = (const float*)d_in[3];
    const float* Wv    = (const float*)d_in[4];
    const float* Wo    = (const float*)d_in[5];
    const float* bo    = (const float*)d_in[6];
    float* out = (float*)d_out;

    bf16 *xh, *xl, *wqh, *wql, *wkh, *wkl, *wvh, *wvl, *woh, *wol;
    bf16 *qh, *ql, *kh, *kl, *vh, *vl, *ch, *cl;
    cudaGetSymbolAddress((void**)&xh, g_xh);   cudaGetSymbolAddress((void**)&xl, g_xl);
    cudaGetSymbolAddress((void**)&wqh, g_wqh); cudaGetSymbolAddress((void**)&wql, g_wql);
    cudaGetSymbolAddress((void**)&wkh, g_wkh); cudaGetSymbolAddress((void**)&wkl, g_wkl);
    cudaGetSymbolAddress((void**)&wvh, g_wvh); cudaGetSymbolAddress((void**)&wvl, g_wvl);
    cudaGetSymbolAddress((void**)&woh, g_woh); cudaGetSymbolAddress((void**)&wol, g_wol);
    cudaGetSymbolAddress((void**)&qh, g_qh);   cudaGetSymbolAddress((void**)&ql, g_ql);
    cudaGetSymbolAddress((void**)&kh, g_kh);   cudaGetSymbolAddress((void**)&kl, g_kl);
    cudaGetSymbolAddress((void**)&vh, g_vh);   cudaGetSymbolAddress((void**)&vl, g_vl);
    cudaGetSymbolAddress((void**)&ch, g_ch);   cudaGetSymbolAddress((void**)&cl, g_cl);

    cudaFuncSetAttribute(gemm_bf3<0>, cudaFuncAttributeMaxDynamicSharedMemorySize, GEMM_SMEM);
    cudaFuncSetAttribute(gemm_bf3<1>, cudaFuncAttributeMaxDynamicSharedMemorySize, GEMM_SMEM);
    cudaFuncSetAttribute(gemm_bf3<2>, cudaFuncAttributeMaxDynamicSharedMemorySize, GEMM_SMEM);
    cudaFuncSetAttribute(attn_bf3, cudaFuncAttributeMaxDynamicSharedMemorySize, ATT_SMEM_BYTES);

    detect_mask_kernel<<<1, 32>>>((const unsigned*)mask);

    const int nq = MM * DDIM, nw = DDIM * DDIM;
    split_f32<<<nq / 512, 256>>>(query, xh, xl, nq);
    split_f32<<<nw / 512, 256>>>(Wq, wqh, wql, nw);
    split_f32<<<nw / 512, 256>>>(Wk, wkh, wkl, nw);
    split_f32<<<nw / 512, 256>>>(Wv, wvh, wvl, nw);
    split_f32<<<nw / 512, 256>>>(Wo, woh, wol, nw);

    dim3 gg(DDIM / 128, MM / 128);
    gemm_bf3<0><<<gg, 256, GEMM_SMEM>>>(xh, xl, wqh, wql, nullptr, qh, ql, nullptr, 0.125f);
    gemm_bf3<0><<<gg, 256, GEMM_SMEM>>>(xh, xl, wkh, wkl, nullptr, kh, kl, nullptr, 1.f);
    gemm_bf3<1><<<gg, 256, GEMM_SMEM>>>(xh, xl, wvh, wvl, nullptr, vh, vl, nullptr, 1.f);

    attn_bf3<<<dim3(SS / 128, BB * HH), 256, ATT_SMEM_BYTES>>>(
        qh, ql, kh, kl, vh, vl, (const uint8_t*)mask, ch, cl);

    gemm_bf3<2><<<gg, 256, GEMM_SMEM>>>(ch, cl, woh, wol, bo, nullptr, nullptr, out, 1.f);
}

// round 12
// speedup vs baseline: 2.8481x; 1.3233x over previous
#include <cuda_runtime.h>
#include <cuda_fp16.h>
#include <stdint.h>

#define BB 2
#define SS 2048
#define DDIM 1024
#define HH 16
#define DH 64
#define MM (BB*SS)

typedef __half fp16;

// -------- global scratch (no cudaMalloc allowed) --------
__device__ fp16 g_xh[(size_t)MM*DDIM],  g_xl[(size_t)MM*DDIM];     // query split
__device__ fp16 g_wq16[(size_t)DDIM*DDIM], g_wk16[(size_t)DDIM*DDIM];
__device__ fp16 g_wv16[(size_t)DDIM*DDIM], g_wo16[(size_t)DDIM*DDIM];
__device__ fp16 g_qh[(size_t)MM*DDIM],  g_ql[(size_t)MM*DDIM];     // [B,H,S,dh]
__device__ fp16 g_k16[(size_t)MM*DDIM];                            // [B,H,S,dh]
__device__ fp16 g_v16[(size_t)MM*DDIM];                            // [B,H,dh,S] transposed
__device__ fp16 g_ch[(size_t)MM*DDIM],  g_cl[(size_t)MM*DDIM];     // ctx [B,S,D]
__device__ int  g_mask_word;

// -------- helpers --------
__device__ __forceinline__ void hsplit(float x, fp16& h, fp16& l) {
    h = __float2half_rn(x);
    l = __float2half_rn(x - __half2float(h));
}
__device__ __forceinline__ uint32_t lds32(const fp16* p) { return *(const uint32_t*)p; }
__device__ __forceinline__ void mma16(float d[4], const uint32_t a[4],
                                      uint32_t b0, uint32_t b1) {
    asm volatile(
        "mma.sync.aligned.m16n8k16.row.col.f32.f16.f16.f32 "
        "{%0,%1,%2,%3},{%4,%5,%6,%7},{%8,%9},{%0,%1,%2,%3};"
        : "+f"(d[0]), "+f"(d[1]), "+f"(d[2]), "+f"(d[3])
        : "r"(a[0]), "r"(a[1]), "r"(a[2]), "r"(a[3]), "r"(b0), "r"(b1));
}
__device__ __forceinline__ void cpa16(void* s, const void* g) {
    uint32_t sa = (uint32_t)__cvta_generic_to_shared(s);
    asm volatile("cp.async.ca.shared.global [%0], [%1], 16;" :: "r"(sa), "l"(g));
}
__device__ __forceinline__ void cpa_commit() { asm volatile("cp.async.commit_group;"); }
__device__ __forceinline__ void cpa_wait0()  { asm volatile("cp.async.wait_group 0;" ::: "memory"); }

// -------- mask dtype detect --------
__global__ void detect_mask_kernel(const unsigned* __restrict__ m) {
    if (threadIdx.x == 0) {
        bool word = true;
        #pragma unroll
        for (int i = 0; i < 16; i++) {
            unsigned v = m[i];
            if (v != 0u && v != 1u && v != 0x3f800000u) word = false;
        }
        g_mask_word = word ? 1 : 0;
    }
}

// -------- fp32 -> fp16 hi/lo split --------
__global__ void __launch_bounds__(256) split_f32(
    const float* __restrict__ x, fp16* __restrict__ h, fp16* __restrict__ l, int n)
{
    int i = (blockIdx.x * 256 + threadIdx.x) * 2;
    if (i < n) {
        float2 v = *(const float2*)(x + i);
        fp16 h0, l0, h1, l1;
        hsplit(v.x, h0, l0);
        hsplit(v.y, h1, l1);
        *(__half2*)(h + i) = __halves2half2(h0, h1);
        *(__half2*)(l + i) = __halves2half2(l0, l1);
    }
}
// -------- fp32 -> fp16 round (weights, B operand) --------
__global__ void __launch_bounds__(256) round_f32(
    const float* __restrict__ x, fp16* __restrict__ h, int n)
{
    int i = (blockIdx.x * 256 + threadIdx.x) * 2;
    if (i < n) {
        float2 v = *(const float2*)(x + i);
        *(__half2*)(h + i) = __halves2half2(__float2half_rn(v.x), __float2half_rn(v.y));
    }
}

// ---------------------------------------------------------------- GEMM fp16x2
// C = scale * (A @ W^T) [+bias].  A: hi/lo fp16 [MM,1024], W: single fp16.
// C = Ah*W + Al*W  (2 MMAs per tile-step).
// MODE 0: split-head [B,H,S,dh] hi+lo out (q)
// MODE 3: split-head [B,H,S,dh] single out (k)
// MODE 1: transposed [B,H,dh,S] single out (v)
// MODE 2: fp32 [MM,1024] + bias (out proj)
// Block 128x128x32, 8 warps (2x4), warp tile 64x32, double-buffered cp.async.
#define GS 40                 // smem row stride in fp16 (80B: conflict-free)
#define TSZ (128*GS)
#define GEMM_SMEM (2*3*TSZ*2) // 61440 bytes: 2 bufs x {Ah,Al,B}

template<int MODE>
__global__ void __launch_bounds__(256, 2) gemm_hf2(
    const fp16* __restrict__ Agh, const fp16* __restrict__ Agl,
    const fp16* __restrict__ Wg,
    const float* __restrict__ bias, fp16* __restrict__ Ch,
    fp16* __restrict__ Cl, float* __restrict__ Co, float scale)
{
    extern __shared__ fp16 smh[];
    const int t = threadIdx.x;
    const int wid = t >> 5, lane = t & 31;
    const int lr = lane >> 2, lc = lane & 3;
    const int m0 = blockIdx.y * 128, n0 = blockIdx.x * 128;
    const int wm = (wid >> 2) * 64, wn = (wid & 3) * 32;

    float acc[4][4][4];
    #pragma unroll
    for (int i = 0; i < 4; i++)
        #pragma unroll
        for (int j = 0; j < 4; j++)
            #pragma unroll
            for (int r = 0; r < 4; r++) acc[i][j][r] = 0.f;

    auto cp_tile = [&](int buf, int k0) {
        fp16* base = smh + buf * 3 * TSZ;
        #pragma unroll
        for (int i = 0; i < 6; i++) {
            const int sub = i >> 1;
            const int j = (i & 1) * 256 + t;     // 0..511
            const int row = j >> 2, ch = (j & 3) * 8;
            const fp16* src;
            if (sub == 0)      src = Agh + (size_t)(m0 + row) * DDIM + k0 + ch;
            else if (sub == 1) src = Agl + (size_t)(m0 + row) * DDIM + k0 + ch;
            else               src = Wg  + (size_t)(n0 + row) * DDIM + k0 + ch;
            cpa16(&base[sub * TSZ + row * GS + ch], src);
        }
        cpa_commit();
    };

    cp_tile(0, 0);
    for (int c = 0; c < 32; c++) {
        cpa_wait0();
        __syncthreads();
        if (c < 31) cp_tile((c + 1) & 1, (c + 1) * 32);
        const fp16* Ahs = smh + (c & 1) * 3 * TSZ;
        const fp16* Als = Ahs + TSZ;
        const fp16* Bs  = Ahs + 2 * TSZ;

        #pragma unroll
        for (int ks = 0; ks < 2; ks++) {
            const int kc = ks * 16 + 2 * lc;
            uint32_t ah[4][4], al[4][4];
            #pragma unroll
            for (int mi = 0; mi < 4; mi++) {
                const int r = wm + mi * 16 + lr;
                ah[mi][0] = lds32(Ahs + (r    ) * GS + kc);
                ah[mi][1] = lds32(Ahs + (r + 8) * GS + kc);
                ah[mi][2] = lds32(Ahs + (r    ) * GS + kc + 8);
                ah[mi][3] = lds32(Ahs + (r + 8) * GS + kc + 8);
                al[mi][0] = lds32(Als + (r    ) * GS + kc);
                al[mi][1] = lds32(Als + (r + 8) * GS + kc);
                al[mi][2] = lds32(Als + (r    ) * GS + kc + 8);
                al[mi][3] = lds32(Als + (r + 8) * GS + kc + 8);
            }
            uint32_t bh[4][2];
            #pragma unroll
            for (int ni = 0; ni < 4; ni++) {
                const int n = wn + ni * 8 + lr;
                bh[ni][0] = lds32(Bs + n * GS + kc);
                bh[ni][1] = lds32(Bs + n * GS + kc + 8);
            }
            #pragma unroll
            for (int mi = 0; mi < 4; mi++)
                #pragma unroll
                for (int ni = 0; ni < 4; ni++) {
                    mma16(acc[mi][ni], ah[mi], bh[ni][0], bh[ni][1]);
                    mma16(acc[mi][ni], al[mi], bh[ni][0], bh[ni][1]);
                }
        }
        __syncthreads();
    }

    // epilogue
    #pragma unroll
    for (int mi = 0; mi < 4; mi++) {
        #pragma unroll
        for (int ni = 0; ni < 4; ni++) {
            const int n = n0 + wn + ni * 8 + 2 * lc;   // even; pair n, n+1
            #pragma unroll
            for (int rr = 0; rr < 2; rr++) {
                const int m = m0 + wm + mi * 16 + lr + rr * 8;
                float v0 = acc[mi][ni][rr * 2 + 0] * scale;
                float v1 = acc[mi][ni][rr * 2 + 1] * scale;
                if (MODE == 2) {
                    Co[(size_t)m * DDIM + n]     = v0 + bias[n];
                    Co[(size_t)m * DDIM + n + 1] = v1 + bias[n + 1];
                } else {
                    const int b = m >> 11, s = m & (SS - 1);
                    const int h = n >> 6,  dd = n & (DH - 1);
                    if (MODE == 0) {
                        fp16 h0, l0, h1, l1;
                        hsplit(v0, h0, l0);
                        hsplit(v1, h1, l1);
                        size_t idx = (((size_t)(b * HH + h) * SS + s) * DH) + dd;
                        *(__half2*)&Ch[idx] = __halves2half2(h0, h1);
                        *(__half2*)&Cl[idx] = __halves2half2(l0, l1);
                    } else if (MODE == 3) {
                        size_t idx = (((size_t)(b * HH + h) * SS + s) * DH) + dd;
                        *(__half2*)&Ch[idx] =
                            __halves2half2(__float2half_rn(v0), __float2half_rn(v1));
                    } else {  // MODE 1: transposed [B,H,dh,S], single fp16
                        size_t idx = (((size_t)(b * HH + h) * DH + dd) * SS) + s;
                        Ch[idx]      = __float2half_rn(v0);
                        Ch[idx + SS] = __float2half_rn(v1);
                    }
                }
            }
        }
    }
}

// ---------------------------------------------------------------- attention
// fp16x2 flash attention. Block: 128 q-rows x one (b,h). 256 threads, 8 warps;
// warp w owns q rows [16w,16w+16). K/V 64-key tiles double-buffered cp.async.
// S = Qh K + Ql K ; O += Ph V + Pl V.
// smem fp16-elem offsets (stride 72 rows = 144B, conflict-free):
#define AQH 0
#define AQL (128*72)
#define AK(b) (2*128*72 + (b)*64*72)
#define AV(b) (2*128*72 + 2*64*72 + (b)*64*72)
#define APH (2*128*72 + 4*64*72)
#define APL (APH + 128*72)
#define AMSK_BYTE ((APL + 128*72) * 2)
#define ATT_SMEM_BYTES (AMSK_BYTE + 2*128*64)

__global__ void __launch_bounds__(256) attn_hf2(
    const fp16* __restrict__ QH, const fp16* __restrict__ QL,
    const fp16* __restrict__ K16, const fp16* __restrict__ V16,
    const uint8_t* __restrict__ maskp,
    fp16* __restrict__ CH, fp16* __restrict__ CL)
{
    extern __shared__ fp16 smh[];
    uint8_t* Mskb = (uint8_t*)smh + AMSK_BYTE;

    const int t = threadIdx.x;
    const int wid = t >> 5, lane = t & 31;
    const int lr = lane >> 2, lc = lane & 3;
    const int w16 = wid * 16;
    const int bh = blockIdx.y;
    const int b = bh >> 4, h = bh & 15;
    const int q0 = blockIdx.x * 128;
    const int mword = g_mask_word;
    const unsigned* mask32 = (const unsigned*)maskp;

    const size_t base = (size_t)bh * SS * DH;   // Q,K: [bh][s][dh] ; V: [bh][dh][s]

    // Q tiles (persistent)
    #pragma unroll
    for (int i = 0; i < 8; i++) {
        const int arr = i >> 2;
        const int j = (i & 3) * 256 + t;       // 0..1023
        const int row = j >> 3, ch = (j & 7) * 8;
        const fp16* src = (arr ? QL : QH) + base + (size_t)(q0 + row) * DH + ch;
        cpa16(&smh[(arr ? AQL : AQH) + row * 72 + ch], src);
    }
    auto cp_kv = [&](int buf, int k0) {
        #pragma unroll
        for (int i = 0; i < 4; i++) {
            const int sub = i >> 1;
            const int j = (i & 1) * 256 + t;   // 0..511
            const int row = j >> 3, ch = (j & 7) * 8;
            const fp16* src;
            int doff;
            if (sub == 0) { src = K16 + base + (size_t)(k0 + row) * DH + ch; doff = AK(buf); }
            else          { src = V16 + base + (size_t)row * SS + k0 + ch;   doff = AV(buf); }
            cpa16(&smh[doff + row * 72 + ch], src);
        }
        cpa_commit();
    };
    cp_kv(0, 0);

    uint32_t mr[8];
    auto ld_mask = [&](int k0) {
        if (mword) {
            #pragma unroll
            for (int i = 0; i < 8; i++) {
                const int id = i * 256 + t;
                const int row = id >> 4, seg = id & 15;
                const unsigned* p = mask32 + ((size_t)(b * SS + q0 + row)) * SS + k0 + seg * 4;
                uint4 u = *(const uint4*)p;
                mr[i] = (u.x ? 1u : 0) | (u.y ? 0x100u : 0)
                      | (u.z ? 0x10000u : 0) | (u.w ? 0x1000000u : 0);
            }
        } else {
            #pragma unroll
            for (int i = 0; i < 2; i++) {
                const int id = i * 256 + t;
                const int row = id >> 2, seg = id & 3;
                const uint8_t* p = maskp + ((size_t)(b * SS + q0 + row)) * SS + k0 + seg * 16;
                uint4 u = *(const uint4*)p;
                mr[i * 4 + 0] = u.x; mr[i * 4 + 1] = u.y;
                mr[i * 4 + 2] = u.z; mr[i * 4 + 3] = u.w;
            }
        }
    };
    auto st_mask = [&](int buf) {
        uint32_t* Mw = (uint32_t*)(Mskb + buf * 8192);
        if (mword) {
            #pragma unroll
            for (int i = 0; i < 8; i++) {
                const int id = i * 256 + t;
                Mw[(id >> 4) * 16 + (id & 15)] = mr[i];
            }
        } else {
            #pragma unroll
            for (int i = 0; i < 2; i++) {
                const int id = i * 256 + t;
                const int row = id >> 2, seg = id & 3;
                #pragma unroll
                for (int j = 0; j < 4; j++) Mw[row * 16 + seg * 4 + j] = mr[i * 4 + j];
            }
        }
    };
    ld_mask(0);
    st_mask(0);

    float m_a = -1e30f, m_b = -1e30f, l_a = 0.f, l_b = 0.f;
    float o[8][4];
    #pragma unroll
    for (int nf = 0; nf < 8; nf++)
        #pragma unroll
        for (int r = 0; r < 4; r++) o[nf][r] = 0.f;

    for (int c = 0; c < SS / 64; c++) {
        cpa_wait0();
        __syncthreads();
        const int buf = c & 1;
        if (c + 1 < SS / 64) {
            cp_kv(buf ^ 1, (c + 1) * 64);
            ld_mask((c + 1) * 64);
        }
        const fp16* kp = smh + AK(buf);
        const fp16* vp = smh + AV(buf);
        const uint8_t* Mb = Mskb + buf * 8192;

        // ---- S = Q K^T  (Qh K + Ql K)
        float s[8][4];
        #pragma unroll
        for (int nf = 0; nf < 8; nf++)
            #pragma unroll
            for (int r = 0; r < 4; r++) s[nf][r] = 0.f;
        #pragma unroll
        for (int ks = 0; ks < 4; ks++) {
            const int kc = ks * 16 + 2 * lc;
            const int r = w16 + lr;
            uint32_t qh[4], ql[4];
            qh[0] = lds32(smh + AQH + (r    ) * 72 + kc);
            qh[1] = lds32(smh + AQH + (r + 8) * 72 + kc);
            qh[2] = lds32(smh + AQH + (r    ) * 72 + kc + 8);
            qh[3] = lds32(smh + AQH + (r + 8) * 72 + kc + 8);
            ql[0] = lds32(smh + AQL + (r    ) * 72 + kc);
            ql[1] = lds32(smh + AQL + (r + 8) * 72 + kc);
            ql[2] = lds32(smh + AQL + (r    ) * 72 + kc + 8);
            ql[3] = lds32(smh + AQL + (r + 8) * 72 + kc + 8);
            #pragma unroll
            for (int nf = 0; nf < 8; nf++) {
                const int n = nf * 8 + lr;
                uint32_t k0v = lds32(kp + n * 72 + kc);
                uint32_t k1v = lds32(kp + n * 72 + kc + 8);
                mma16(s[nf], qh, k0v, k1v);
                mma16(s[nf], ql, k0v, k1v);
            }
        }

        // ---- mask + online softmax
        const int ra = w16 + lr, rb = ra + 8;
        float mxa = -1e30f, mxb = -1e30f;
        #pragma unroll
        for (int nf = 0; nf < 8; nf++) {
            const int c0 = nf * 8 + 2 * lc;
            if (Mb[ra * 64 + c0    ]) s[nf][0] = -1e30f;
            if (Mb[ra * 64 + c0 + 1]) s[nf][1] = -1e30f;
            if (Mb[rb * 64 + c0    ]) s[nf][2] = -1e30f;
            if (Mb[rb * 64 + c0 + 1]) s[nf][3] = -1e30f;
            mxa = fmaxf(mxa, fmaxf(s[nf][0], s[nf][1]));
            mxb = fmaxf(mxb, fmaxf(s[nf][2], s[nf][3]));
        }
        mxa = fmaxf(mxa, __shfl_xor_sync(0xFFFFFFFFu, mxa, 1));
        mxa = fmaxf(mxa, __shfl_xor_sync(0xFFFFFFFFu, mxa, 2));
        mxb = fmaxf(mxb, __shfl_xor_sync(0xFFFFFFFFu, mxb, 1));
        mxb = fmaxf(mxb, __shfl_xor_sync(0xFFFFFFFFu, mxb, 2));
        float mna = fmaxf(m_a, mxa), mnb = fmaxf(m_b, mxb);
        float ca = __expf(m_a - mna), cb = __expf(m_b - mnb);
        float sa = 0.f, sb = 0.f;
        #pragma unroll
        for (int nf = 0; nf < 8; nf++) {
            const int c0 = nf * 8 + 2 * lc;
            float p0 = (s[nf][0] <= -1e29f) ? 0.f : __expf(s[nf][0] - mna);
            float p1 = (s[nf][1] <= -1e29f) ? 0.f : __expf(s[nf][1] - mna);
            float p2 = (s[nf][2] <= -1e29f) ? 0.f : __expf(s[nf][2] - mnb);
            float p3 = (s[nf][3] <= -1e29f) ? 0.f : __expf(s[nf][3] - mnb);
            sa += p0 + p1; sb += p2 + p3;
            fp16 h0, l0, h1, l1;
            hsplit(p0, h0, l0); hsplit(p1, h1, l1);
            *(__half2*)&smh[APH + ra * 72 + c0] = __halves2half2(h0, h1);
            *(__half2*)&smh[APL + ra * 72 + c0] = __halves2half2(l0, l1);
            hsplit(p2, h0, l0); hsplit(p3, h1, l1);
            *(__half2*)&smh[APH + rb * 72 + c0] = __halves2half2(h0, h1);
            *(__half2*)&smh[APL + rb * 72 + c0] = __halves2half2(l0, l1);
        }
        sa += __shfl_xor_sync(0xFFFFFFFFu, sa, 1);
        sa += __shfl_xor_sync(0xFFFFFFFFu, sa, 2);
        sb += __shfl_xor_sync(0xFFFFFFFFu, sb, 1);
        sb += __shfl_xor_sync(0xFFFFFFFFu, sb, 2);
        l_a = l_a * ca + sa; l_b = l_b * cb + sb;
        m_a = mna; m_b = mnb;
        #pragma unroll
        for (int nf = 0; nf < 8; nf++) {
            o[nf][0] *= ca; o[nf][1] *= ca; o[nf][2] *= cb; o[nf][3] *= cb;
        }
        __syncwarp();  // each warp consumes only its own P rows

        // ---- O += P V  (Ph V + Pl V); V tile is [dh][key] (k-contig)
        #pragma unroll
        for (int ks = 0; ks < 4; ks++) {
            const int kc = ks * 16 + 2 * lc;
            const int r = w16 + lr;
            uint32_t ph[4], pl[4];
            ph[0] = lds32(smh + APH + (r    ) * 72 + kc);
            ph[1] = lds32(smh + APH + (r + 8) * 72 + kc);
            ph[2] = lds32(smh + APH + (r    ) * 72 + kc + 8);
            ph[3] = lds32(smh + APH + (r + 8) * 72 + kc + 8);
            pl[0] = lds32(smh + APL + (r    ) * 72 + kc);
            pl[1] = lds32(smh + APL + (r + 8) * 72 + kc);
            pl[2] = lds32(smh + APL + (r    ) * 72 + kc + 8);
            pl[3] = lds32(smh + APL + (r + 8) * 72 + kc + 8);
            #pragma unroll
            for (int nf = 0; nf < 8; nf++) {
                const int n = nf * 8 + lr;
                uint32_t v0 = lds32(vp + n * 72 + kc);
                uint32_t v1 = lds32(vp + n * 72 + kc + 8);
                mma16(o[nf], ph, v0, v1);
                mma16(o[nf], pl, v0, v1);
            }
        }

        if (c + 1 < SS / 64) st_mask(buf ^ 1);
    }

    // ---- epilogue: normalize, split, write ctx hi/lo [B,S,D]
    const float inva = (l_a > 0.f) ? (1.f / l_a) : 0.f;
    const float invb = (l_b > 0.f) ? (1.f / l_b) : 0.f;
    const int qa = q0 + w16 + lr, qb = qa + 8;
    #pragma unroll
    for (int nf = 0; nf < 8; nf++) {
        const int dd = h * DH + nf * 8 + 2 * lc;
        fp16 h0, l0, h1, l1;
        hsplit(o[nf][0] * inva, h0, l0); hsplit(o[nf][1] * inva, h1, l1);
        size_t ia = (size_t)(b * SS + qa) * DDIM + dd;
        *(__half2*)&CH[ia] = __halves2half2(h0, h1);
        *(__half2*)&CL[ia] = __halves2half2(l0, l1);
        hsplit(o[nf][2] * invb, h0, l0); hsplit(o[nf][3] * invb, h1, l1);
        size_t ib = (size_t)(b * SS + qb) * DDIM + dd;
        *(__half2*)&CH[ib] = __halves2half2(h0, h1);
        *(__half2*)&CL[ib] = __halves2half2(l0, l1);
    }
}

// ---------------------------------------------------------------- launcher
extern "C" void kernel_launch(void* const* d_in, const int* in_sizes, int n_in,
                              void* d_out, int out_size)
{
    const float* query = (const float*)d_in[0];
    const void*  mask  = d_in[1];
    const float* Wq    = (const float*)d_in[2];
    const float* Wk    = (const float*)d_in[3];
    const float* Wv    = (const float*)d_in[4];
    const float* Wo    = (const float*)d_in[5];
    const float* bo    = (const float*)d_in[6];
    float* out = (float*)d_out;

    fp16 *xh, *xl, *wq16, *wk16, *wv16, *wo16;
    fp16 *qh, *ql, *k16, *v16, *ch, *cl;
    cudaGetSymbolAddress((void**)&xh, g_xh);     cudaGetSymbolAddress((void**)&xl, g_xl);
    cudaGetSymbolAddress((void**)&wq16, g_wq16); cudaGetSymbolAddress((void**)&wk16, g_wk16);
    cudaGetSymbolAddress((void**)&wv16, g_wv16); cudaGetSymbolAddress((void**)&wo16, g_wo16);
    cudaGetSymbolAddress((void**)&qh, g_qh);     cudaGetSymbolAddress((void**)&ql, g_ql);
    cudaGetSymbolAddress((void**)&k16, g_k16);   cudaGetSymbolAddress((void**)&v16, g_v16);
    cudaGetSymbolAddress((void**)&ch, g_ch);     cudaGetSymbolAddress((void**)&cl, g_cl);

    cudaFuncSetAttribute(gemm_hf2<0>, cudaFuncAttributeMaxDynamicSharedMemorySize, GEMM_SMEM);
    cudaFuncSetAttribute(gemm_hf2<1>, cudaFuncAttributeMaxDynamicSharedMemorySize, GEMM_SMEM);
    cudaFuncSetAttribute(gemm_hf2<2>, cudaFuncAttributeMaxDynamicSharedMemorySize, GEMM_SMEM);
    cudaFuncSetAttribute(gemm_hf2<3>, cudaFuncAttributeMaxDynamicSharedMemorySize, GEMM_SMEM);
    cudaFuncSetAttribute(attn_hf2, cudaFuncAttributeMaxDynamicSharedMemorySize, ATT_SMEM_BYTES);

    detect_mask_kernel<<<1, 32>>>((const unsigned*)mask);

    const int nq = MM * DDIM, nw = DDIM * DDIM;
    split_f32<<<nq / 512, 256>>>(query, xh, xl, nq);
    round_f32<<<nw / 512, 256>>>(Wq, wq16, nw);
    round_f32<<<nw / 512, 256>>>(Wk, wk16, nw);
    round_f32<<<nw / 512, 256>>>(Wv, wv16, nw);
    round_f32<<<nw / 512, 256>>>(Wo, wo16, nw);

    dim3 gg(DDIM / 128, MM / 128);
    gemm_hf2<0><<<gg, 256, GEMM_SMEM>>>(xh, xl, wq16, nullptr, qh, ql, nullptr, 0.125f);
    gemm_hf2<3><<<gg, 256, GEMM_SMEM>>>(xh, xl, wk16, nullptr, k16, nullptr, nullptr, 1.f);
    gemm_hf2<1><<<gg, 256, GEMM_SMEM>>>(xh, xl, wv16, nullptr, v16, nullptr, nullptr, 1.f);

    attn_hf2<<<dim3(SS / 128, BB * HH), 256, ATT_SMEM_BYTES>>>(
        qh, ql, k16, v16, (const uint8_t*)mask, ch, cl);

    gemm_hf2<2><<<gg, 256, GEMM_SMEM>>>(ch, cl, wo16, bo, nullptr, nullptr, out, 1.f);
}

// round 13
// speedup vs baseline: 3.6793x; 1.2918x over previous
#include <cuda_runtime.h>
#include <cuda_fp16.h>
#include <stdint.h>

#define BB 2
#define SS 2048
#define DDIM 1024
#define HH 16
#define DH 64
#define MM (BB*SS)

typedef __half fp16;

// -------- global scratch (no cudaMalloc allowed) --------
__device__ fp16 g_xh[(size_t)MM*DDIM],  g_xl[(size_t)MM*DDIM];     // query split
__device__ fp16 g_wq16[(size_t)DDIM*DDIM], g_wk16[(size_t)DDIM*DDIM];
__device__ fp16 g_wv16[(size_t)DDIM*DDIM], g_wo16[(size_t)DDIM*DDIM];
__device__ fp16 g_q16[(size_t)MM*DDIM];                            // [B,H,S,dh] single
__device__ fp16 g_k16[(size_t)MM*DDIM];                            // [B,H,S,dh] single
__device__ fp16 g_v16[(size_t)MM*DDIM];                            // [B,H,dh,S] transposed
__device__ fp16 g_ch[(size_t)MM*DDIM],  g_cl[(size_t)MM*DDIM];     // ctx [B,S,D] split
__device__ int  g_mask_word;

// -------- helpers --------
__device__ __forceinline__ void hsplit(float x, fp16& h, fp16& l) {
    h = __float2half_rn(x);
    l = __float2half_rn(x - __half2float(h));
}
__device__ __forceinline__ uint32_t lds32(const fp16* p) { return *(const uint32_t*)p; }
__device__ __forceinline__ void mma16(float d[4], const uint32_t a[4],
                                      uint32_t b0, uint32_t b1) {
    asm volatile(
        "mma.sync.aligned.m16n8k16.row.col.f32.f16.f16.f32 "
        "{%0,%1,%2,%3},{%4,%5,%6,%7},{%8,%9},{%0,%1,%2,%3};"
        : "+f"(d[0]), "+f"(d[1]), "+f"(d[2]), "+f"(d[3])
        : "r"(a[0]), "r"(a[1]), "r"(a[2]), "r"(a[3]), "r"(b0), "r"(b1));
}
__device__ __forceinline__ void cpa16(void* s, const void* g) {
    uint32_t sa = (uint32_t)__cvta_generic_to_shared(s);
    asm volatile("cp.async.ca.shared.global [%0], [%1], 16;" :: "r"(sa), "l"(g));
}
__device__ __forceinline__ void cpa_commit() { asm volatile("cp.async.commit_group;"); }
__device__ __forceinline__ void cpa_wait0()  { asm volatile("cp.async.wait_group 0;" ::: "memory"); }

// -------- mask dtype detect --------
__global__ void detect_mask_kernel(const unsigned* __restrict__ m) {
    if (threadIdx.x == 0) {
        bool word = true;
        #pragma unroll
        for (int i = 0; i < 16; i++) {
            unsigned v = m[i];
            if (v != 0u && v != 1u && v != 0x3f800000u) word = false;
        }
        g_mask_word = word ? 1 : 0;
    }
}

// -------- fp32 -> fp16 hi/lo split (query only) --------
__global__ void __launch_bounds__(256) split_f32(
    const float* __restrict__ x, fp16* __restrict__ h, fp16* __restrict__ l, int n)
{
    int i = (blockIdx.x * 256 + threadIdx.x) * 2;
    if (i < n) {
        float2 v = *(const float2*)(x + i);
        fp16 h0, l0, h1, l1;
        hsplit(v.x, h0, l0);
        hsplit(v.y, h1, l1);
        *(__half2*)(h + i) = __halves2half2(h0, h1);
        *(__half2*)(l + i) = __halves2half2(l0, l1);
    }
}
// -------- all 4 weights -> fp16 in one launch --------
#define NW (DDIM*DDIM)
__global__ void __launch_bounds__(256) round4_f32(
    const float* __restrict__ a, const float* __restrict__ b,
    const float* __restrict__ c, const float* __restrict__ d,
    fp16* __restrict__ oa, fp16* __restrict__ ob,
    fp16* __restrict__ oc, fp16* __restrict__ od)
{
    const int sel = blockIdx.x >> 11;                  // 2048 blocks per weight
    const int off = ((blockIdx.x & 2047) * 256 + threadIdx.x) * 2;
    const float* src = (sel == 0) ? a : (sel == 1) ? b : (sel == 2) ? c : d;
    fp16* dst = (sel == 0) ? oa : (sel == 1) ? ob : (sel == 2) ? oc : od;
    float2 v = *(const float2*)(src + off);
    *(__half2*)(dst + off) = __halves2half2(__float2half_rn(v.x), __float2half_rn(v.y));
}

// ---------------------------------------------------------------- GEMM fp16x2
// C = scale * (A @ W^T) [+bias].  A: hi/lo fp16, W: single fp16.
// C = Ah*W + Al*W.
// MODE 3: split-head [B,H,S,dh] single out (q,k)
// MODE 1: transposed [B,H,dh,S] single out (v)
// MODE 2: fp32 [MM,1024] + bias (out proj)
#define GS 40
#define TSZ (128*GS)
#define GEMM_SMEM (2*3*TSZ*2)

template<int MODE>
__global__ void __launch_bounds__(256, 2) gemm_hf2(
    const fp16* __restrict__ Agh, const fp16* __restrict__ Agl,
    const fp16* __restrict__ Wg,
    const float* __restrict__ bias, fp16* __restrict__ Ch,
    float* __restrict__ Co, float scale)
{
    extern __shared__ fp16 smh[];
    const int t = threadIdx.x;
    const int wid = t >> 5, lane = t & 31;
    const int lr = lane >> 2, lc = lane & 3;
    const int m0 = blockIdx.y * 128, n0 = blockIdx.x * 128;
    const int wm = (wid >> 2) * 64, wn = (wid & 3) * 32;

    float acc[4][4][4];
    #pragma unroll
    for (int i = 0; i < 4; i++)
        #pragma unroll
        for (int j = 0; j < 4; j++)
            #pragma unroll
            for (int r = 0; r < 4; r++) acc[i][j][r] = 0.f;

    auto cp_tile = [&](int buf, int k0) {
        fp16* base = smh + buf * 3 * TSZ;
        #pragma unroll
        for (int i = 0; i < 6; i++) {
            const int sub = i >> 1;
            const int j = (i & 1) * 256 + t;
            const int row = j >> 2, ch = (j & 3) * 8;
            const fp16* src;
            if (sub == 0)      src = Agh + (size_t)(m0 + row) * DDIM + k0 + ch;
            else if (sub == 1) src = Agl + (size_t)(m0 + row) * DDIM + k0 + ch;
            else               src = Wg  + (size_t)(n0 + row) * DDIM + k0 + ch;
            cpa16(&base[sub * TSZ + row * GS + ch], src);
        }
        cpa_commit();
    };

    cp_tile(0, 0);
    for (int c = 0; c < 32; c++) {
        cpa_wait0();
        __syncthreads();
        if (c < 31) cp_tile((c + 1) & 1, (c + 1) * 32);
        const fp16* Ahs = smh + (c & 1) * 3 * TSZ;
        const fp16* Als = Ahs + TSZ;
        const fp16* Bs  = Ahs + 2 * TSZ;

        #pragma unroll
        for (int ks = 0; ks < 2; ks++) {
            const int kc = ks * 16 + 2 * lc;
            uint32_t ah[4][4], al[4][4];
            #pragma unroll
            for (int mi = 0; mi < 4; mi++) {
                const int r = wm + mi * 16 + lr;
                ah[mi][0] = lds32(Ahs + (r    ) * GS + kc);
                ah[mi][1] = lds32(Ahs + (r + 8) * GS + kc);
                ah[mi][2] = lds32(Ahs + (r    ) * GS + kc + 8);
                ah[mi][3] = lds32(Ahs + (r + 8) * GS + kc + 8);
                al[mi][0] = lds32(Als + (r    ) * GS + kc);
                al[mi][1] = lds32(Als + (r + 8) * GS + kc);
                al[mi][2] = lds32(Als + (r    ) * GS + kc + 8);
                al[mi][3] = lds32(Als + (r + 8) * GS + kc + 8);
            }
            uint32_t bh[4][2];
            #pragma unroll
            for (int ni = 0; ni < 4; ni++) {
                const int n = wn + ni * 8 + lr;
                bh[ni][0] = lds32(Bs + n * GS + kc);
                bh[ni][1] = lds32(Bs + n * GS + kc + 8);
            }
            #pragma unroll
            for (int mi = 0; mi < 4; mi++)
                #pragma unroll
                for (int ni = 0; ni < 4; ni++) {
                    mma16(acc[mi][ni], ah[mi], bh[ni][0], bh[ni][1]);
                    mma16(acc[mi][ni], al[mi], bh[ni][0], bh[ni][1]);
                }
        }
        __syncthreads();
    }

    // epilogue
    #pragma unroll
    for (int mi = 0; mi < 4; mi++) {
        #pragma unroll
        for (int ni = 0; ni < 4; ni++) {
            const int n = n0 + wn + ni * 8 + 2 * lc;
            #pragma unroll
            for (int rr = 0; rr < 2; rr++) {
                const int m = m0 + wm + mi * 16 + lr + rr * 8;
                float v0 = acc[mi][ni][rr * 2 + 0] * scale;
                float v1 = acc[mi][ni][rr * 2 + 1] * scale;
                if (MODE == 2) {
                    Co[(size_t)m * DDIM + n]     = v0 + bias[n];
                    Co[(size_t)m * DDIM + n + 1] = v1 + bias[n + 1];
                } else {
                    const int b = m >> 11, s = m & (SS - 1);
                    const int h = n >> 6,  dd = n & (DH - 1);
                    if (MODE == 3) {
                        size_t idx = (((size_t)(b * HH + h) * SS + s) * DH) + dd;
                        *(__half2*)&Ch[idx] =
                            __halves2half2(__float2half_rn(v0), __float2half_rn(v1));
                    } else {  // MODE 1: transposed [B,H,dh,S]
                        size_t idx = (((size_t)(b * HH + h) * DH + dd) * SS) + s;
                        Ch[idx]      = __float2half_rn(v0);
                        Ch[idx + SS] = __float2half_rn(v1);
                    }
                }
            }
        }
    }
}

// ---------------------------------------------------------------- attention
// fp16 flash attention, single-precision fragments everywhere (Q,K,P,V single).
// Block: 128 q-rows x one (b,h). 256 threads, 8 warps; warp w owns q rows
// [16w,16w+16). K/V 64-key tiles double-buffered via cp.async.
// smem fp16-elem offsets (stride 72 rows = 144B, conflict-free):
#define AQ 0
#define AK(b) (128*72 + (b)*64*72)
#define AV(b) (128*72 + 2*64*72 + (b)*64*72)
#define AP (128*72 + 4*64*72)
#define AMSK_BYTE ((AP + 128*72) * 2)
#define ATT_SMEM_BYTES (AMSK_BYTE + 2*128*64)   // ~90KB -> 2 CTAs/SM

__global__ void __launch_bounds__(256, 2) attn_hf1(
    const fp16* __restrict__ Q16, const fp16* __restrict__ K16,
    const fp16* __restrict__ V16, const uint8_t* __restrict__ maskp,
    fp16* __restrict__ CH, fp16* __restrict__ CL)
{
    extern __shared__ fp16 smh[];
    uint8_t* Mskb = (uint8_t*)smh + AMSK_BYTE;

    const int t = threadIdx.x;
    const int wid = t >> 5, lane = t & 31;
    const int lr = lane >> 2, lc = lane & 3;
    const int w16 = wid * 16;
    const int bh = blockIdx.y;
    const int b = bh >> 4, h = bh & 15;
    const int q0 = blockIdx.x * 128;
    const int mword = g_mask_word;
    const unsigned* mask32 = (const unsigned*)maskp;

    const size_t base = (size_t)bh * SS * DH;   // Q,K: [bh][s][dh] ; V: [bh][dh][s]

    // Q tile (persistent, single)
    #pragma unroll
    for (int i = 0; i < 4; i++) {
        const int j = i * 256 + t;             // 0..1023
        const int row = j >> 3, ch = (j & 7) * 8;
        cpa16(&smh[AQ + row * 72 + ch], Q16 + base + (size_t)(q0 + row) * DH + ch);
    }
    auto cp_kv = [&](int buf, int k0) {
        #pragma unroll
        for (int i = 0; i < 4; i++) {
            const int sub = i >> 1;
            const int j = (i & 1) * 256 + t;   // 0..511
            const int row = j >> 3, ch = (j & 7) * 8;
            const fp16* src;
            int doff;
            if (sub == 0) { src = K16 + base + (size_t)(k0 + row) * DH + ch; doff = AK(buf); }
            else          { src = V16 + base + (size_t)row * SS + k0 + ch;   doff = AV(buf); }
            cpa16(&smh[doff + row * 72 + ch], src);
        }
        cpa_commit();
    };
    cp_kv(0, 0);

    uint32_t mr[8];
    auto ld_mask = [&](int k0) {
        if (mword) {
            #pragma unroll
            for (int i = 0; i < 8; i++) {
                const int id = i * 256 + t;
                const int row = id >> 4, seg = id & 15;
                const unsigned* p = mask32 + ((size_t)(b * SS + q0 + row)) * SS + k0 + seg * 4;
                uint4 u = *(const uint4*)p;
                mr[i] = (u.x ? 1u : 0) | (u.y ? 0x100u : 0)
                      | (u.z ? 0x10000u : 0) | (u.w ? 0x1000000u : 0);
            }
        } else {
            #pragma unroll
            for (int i = 0; i < 2; i++) {
                const int id = i * 256 + t;
                const int row = id >> 2, seg = id & 3;
                const uint8_t* p = maskp + ((size_t)(b * SS + q0 + row)) * SS + k0 + seg * 16;
                uint4 u = *(const uint4*)p;
                mr[i * 4 + 0] = u.x; mr[i * 4 + 1] = u.y;
                mr[i * 4 + 2] = u.z; mr[i * 4 + 3] = u.w;
            }
        }
    };
    auto st_mask = [&](int buf) {
        uint32_t* Mw = (uint32_t*)(Mskb + buf * 8192);
        if (mword) {
            #pragma unroll
            for (int i = 0; i < 8; i++) {
                const int id = i * 256 + t;
                Mw[(id >> 4) * 16 + (id & 15)] = mr[i];
            }
        } else {
            #pragma unroll
            for (int i = 0; i < 2; i++) {
                const int id = i * 256 + t;
                const int row = id >> 2, seg = id & 3;
                #pragma unroll
                for (int j = 0; j < 4; j++) Mw[row * 16 + seg * 4 + j] = mr[i * 4 + j];
            }
        }
    };
    ld_mask(0);
    st_mask(0);

    float m_a = -1e30f, m_b = -1e30f, l_a = 0.f, l_b = 0.f;
    float o[8][4];
    #pragma unroll
    for (int nf = 0; nf < 8; nf++)
        #pragma unroll
        for (int r = 0; r < 4; r++) o[nf][r] = 0.f;

    for (int c = 0; c < SS / 64; c++) {
        cpa_wait0();
        __syncthreads();
        const int buf = c & 1;
        if (c + 1 < SS / 64) {
            cp_kv(buf ^ 1, (c + 1) * 64);
            ld_mask((c + 1) * 64);
        }
        const fp16* kp = smh + AK(buf);
        const fp16* vp = smh + AV(buf);
        const uint8_t* Mb = Mskb + buf * 8192;

        // ---- S = Q K^T (single x single)
        float s[8][4];
        #pragma unroll
        for (int nf = 0; nf < 8; nf++)
            #pragma unroll
            for (int r = 0; r < 4; r++) s[nf][r] = 0.f;
        #pragma unroll
        for (int ks = 0; ks < 4; ks++) {
            const int kc = ks * 16 + 2 * lc;
            const int r = w16 + lr;
            uint32_t q[4];
            q[0] = lds32(smh + AQ + (r    ) * 72 + kc);
            q[1] = lds32(smh + AQ + (r + 8) * 72 + kc);
            q[2] = lds32(smh + AQ + (r    ) * 72 + kc + 8);
            q[3] = lds32(smh + AQ + (r + 8) * 72 + kc + 8);
            #pragma unroll
            for (int nf = 0; nf < 8; nf++) {
                const int n = nf * 8 + lr;
                uint32_t k0v = lds32(kp + n * 72 + kc);
                uint32_t k1v = lds32(kp + n * 72 + kc + 8);
                mma16(s[nf], q, k0v, k1v);
            }
        }

        // ---- mask + online softmax
        const int ra = w16 + lr, rb = ra + 8;
        float mxa = -1e30f, mxb = -1e30f;
        #pragma unroll
        for (int nf = 0; nf < 8; nf++) {
            const int c0 = nf * 8 + 2 * lc;
            if (Mb[ra * 64 + c0    ]) s[nf][0] = -1e30f;
            if (Mb[ra * 64 + c0 + 1]) s[nf][1] = -1e30f;
            if (Mb[rb * 64 + c0    ]) s[nf][2] = -1e30f;
            if (Mb[rb * 64 + c0 + 1]) s[nf][3] = -1e30f;
            mxa = fmaxf(mxa, fmaxf(s[nf][0], s[nf][1]));
            mxb = fmaxf(mxb, fmaxf(s[nf][2], s[nf][3]));
        }
        mxa = fmaxf(mxa, __shfl_xor_sync(0xFFFFFFFFu, mxa, 1));
        mxa = fmaxf(mxa, __shfl_xor_sync(0xFFFFFFFFu, mxa, 2));
        mxb = fmaxf(mxb, __shfl_xor_sync(0xFFFFFFFFu, mxb, 1));
        mxb = fmaxf(mxb, __shfl_xor_sync(0xFFFFFFFFu, mxb, 2));
        float mna = fmaxf(m_a, mxa), mnb = fmaxf(m_b, mxb);
        float ca = __expf(m_a - mna), cb = __expf(m_b - mnb);
        float sa = 0.f, sb = 0.f;
        #pragma unroll
        for (int nf = 0; nf < 8; nf++) {
            const int c0 = nf * 8 + 2 * lc;
            float p0 = (s[nf][0] <= -1e29f) ? 0.f : __expf(s[nf][0] - mna);
            float p1 = (s[nf][1] <= -1e29f) ? 0.f : __expf(s[nf][1] - mna);
            float p2 = (s[nf][2] <= -1e29f) ? 0.f : __expf(s[nf][2] - mnb);
            float p3 = (s[nf][3] <= -1e29f) ? 0.f : __expf(s[nf][3] - mnb);
            sa += p0 + p1; sb += p2 + p3;
            *(__half2*)&smh[AP + ra * 72 + c0] =
                __halves2half2(__float2half_rn(p0), __float2half_rn(p1));
            *(__half2*)&smh[AP + rb * 72 + c0] =
                __halves2half2(__float2half_rn(p2), __float2half_rn(p3));
        }
        sa += __shfl_xor_sync(0xFFFFFFFFu, sa, 1);
        sa += __shfl_xor_sync(0xFFFFFFFFu, sa, 2);
        sb += __shfl_xor_sync(0xFFFFFFFFu, sb, 1);
        sb += __shfl_xor_sync(0xFFFFFFFFu, sb, 2);
        l_a = l_a * ca + sa; l_b = l_b * cb + sb;
        m_a = mna; m_b = mnb;
        #pragma unroll
        for (int nf = 0; nf < 8; nf++) {
            o[nf][0] *= ca; o[nf][1] *= ca; o[nf][2] *= cb; o[nf][3] *= cb;
        }
        __syncwarp();  // each warp consumes only its own P rows

        // ---- O += P V  (single P); V tile is [dh][key] (k-contig)
        #pragma unroll
        for (int ks = 0; ks < 4; ks++) {
            const int kc = ks * 16 + 2 * lc;
            const int r = w16 + lr;
            uint32_t ph[4];
            ph[0] = lds32(smh + AP + (r    ) * 72 + kc);
            ph[1] = lds32(smh + AP + (r + 8) * 72 + kc);
            ph[2] = lds32(smh + AP + (r    ) * 72 + kc + 8);
            ph[3] = lds32(smh + AP + (r + 8) * 72 + kc + 8);
            #pragma unroll
            for (int nf = 0; nf < 8; nf++) {
                const int n = nf * 8 + lr;
                uint32_t v0 = lds32(vp + n * 72 + kc);
                uint32_t v1 = lds32(vp + n * 72 + kc + 8);
                mma16(o[nf], ph, v0, v1);
            }
        }

        if (c + 1 < SS / 64) st_mask(buf ^ 1);
    }

    // ---- epilogue: normalize, split, write ctx hi/lo [B,S,D]
    const float inva = (l_a > 0.f) ? (1.f / l_a) : 0.f;
    const float invb = (l_b > 0.f) ? (1.f / l_b) : 0.f;
    const int qa = q0 + w16 + lr, qb = qa + 8;
    #pragma unroll
    for (int nf = 0; nf < 8; nf++) {
        const int dd = h * DH + nf * 8 + 2 * lc;
        fp16 h0, l0, h1, l1;
        hsplit(o[nf][0] * inva, h0, l0); hsplit(o[nf][1] * inva, h1, l1);
        size_t ia = (size_t)(b * SS + qa) * DDIM + dd;
        *(__half2*)&CH[ia] = __halves2half2(h0, h1);
        *(__half2*)&CL[ia] = __halves2half2(l0, l1);
        hsplit(o[nf][2] * invb, h0, l0); hsplit(o[nf][3] * invb, h1, l1);
        size_t ib = (size_t)(b * SS + qb) * DDIM + dd;
        *(__half2*)&CH[ib] = __halves2half2(h0, h1);
        *(__half2*)&CL[ib] = __halves2half2(l0, l1);
    }
}

// ---------------------------------------------------------------- launcher
extern "C" void kernel_launch(void* const* d_in, const int* in_sizes, int n_in,
                              void* d_out, int out_size)
{
    const float* query = (const float*)d_in[0];
    const void*  mask  = d_in[1];
    const float* Wq    = (const float*)d_in[2];
    const float* Wk    = (const float*)d_in[3];
    const float* Wv    = (const float*)d_in[4];
    const float* Wo    = (const float*)d_in[5];
    const float* bo    = (const float*)d_in[6];
    float* out = (float*)d_out;

    fp16 *xh, *xl, *wq16, *wk16, *wv16, *wo16;
    fp16 *q16, *k16, *v16, *ch, *cl;
    cudaGetSymbolAddress((void**)&xh, g_xh);     cudaGetSymbolAddress((void**)&xl, g_xl);
    cudaGetSymbolAddress((void**)&wq16, g_wq16); cudaGetSymbolAddress((void**)&wk16, g_wk16);
    cudaGetSymbolAddress((void**)&wv16, g_wv16); cudaGetSymbolAddress((void**)&wo16, g_wo16);
    cudaGetSymbolAddress((void**)&q16, g_q16);   cudaGetSymbolAddress((void**)&k16, g_k16);
    cudaGetSymbolAddress((void**)&v16, g_v16);
    cudaGetSymbolAddress((void**)&ch, g_ch);     cudaGetSymbolAddress((void**)&cl, g_cl);

    cudaFuncSetAttribute(gemm_hf2<1>, cudaFuncAttributeMaxDynamicSharedMemorySize, GEMM_SMEM);
    cudaFuncSetAttribute(gemm_hf2<2>, cudaFuncAttributeMaxDynamicSharedMemorySize, GEMM_SMEM);
    cudaFuncSetAttribute(gemm_hf2<3>, cudaFuncAttributeMaxDynamicSharedMemorySize, GEMM_SMEM);
    cudaFuncSetAttribute(attn_hf1, cudaFuncAttributeMaxDynamicSharedMemorySize, ATT_SMEM_BYTES);

    detect_mask_kernel<<<1, 32>>>((const unsigned*)mask);

    const int nq = MM * DDIM;
    split_f32<<<nq / 512, 256>>>(query, xh, xl, nq);
    round4_f32<<<4 * NW / 512, 256>>>(Wq, Wk, Wv, Wo, wq16, wk16, wv16, wo16);

    dim3 gg(DDIM / 128, MM / 128);
    gemm_hf2<3><<<gg, 256, GEMM_SMEM>>>(xh, xl, wq16, nullptr, q16, nullptr, 0.125f);
    gemm_hf2<3><<<gg, 256, GEMM_SMEM>>>(xh, xl, wk16, nullptr, k16, nullptr, 1.f);
    gemm_hf2<1><<<gg, 256, GEMM_SMEM>>>(xh, xl, wv16, nullptr, v16, nullptr, 1.f);

    attn_hf1<<<dim3(SS / 128, BB * HH), 256, ATT_SMEM_BYTES>>>(
        q16, k16, v16, (const uint8_t*)mask, ch, cl);

    gemm_hf2<2><<<gg, 256, GEMM_SMEM>>>(ch, cl, wo16, bo, nullptr, out, 1.f);
}

// round 17
// speedup vs baseline: 4.3460x; 1.1812x over previous
#include <cuda_runtime.h>
#include <cuda_fp16.h>
#include <stdint.h>

#define BB 2
#define SS 2048
#define DDIM 1024
#define HH 16
#define DH 64
#define MM (BB*SS)

typedef __half fp16;

// -------- global scratch (no cudaMalloc allowed) --------
// g_x16 holds the fp16 query for the projections; after gemm_qkv completes it
// is dead, so the attention kernel reuses it as ctx-hi (stream-ordered).
__device__ fp16 g_x16[(size_t)MM*DDIM];                            // x16, then ctx-hi
__device__ fp16 g_wq16[(size_t)DDIM*DDIM], g_wk16[(size_t)DDIM*DDIM];
__device__ fp16 g_wv16[(size_t)DDIM*DDIM], g_wo16[(size_t)DDIM*DDIM];
__device__ fp16 g_q16[(size_t)MM*DDIM];                            // [B,H,S,dh]
__device__ fp16 g_k16[(size_t)MM*DDIM];                            // [B,H,S,dh]
__device__ fp16 g_v16[(size_t)MM*DDIM];                            // [B,H,dh,S] transposed
__device__ fp16 g_cl[(size_t)MM*DDIM];                             // ctx-lo [B,S,D]
__device__ int  g_mask_word;

// -------- helpers --------
__device__ __forceinline__ void hsplit(float x, fp16& h, fp16& l) {
    h = __float2half_rn(x);
    l = __float2half_rn(x - __half2float(h));
}
__device__ __forceinline__ uint32_t lds32(const fp16* p) { return *(const uint32_t*)p; }
__device__ __forceinline__ void mma16(float d[4], const uint32_t a[4],
                                      uint32_t b0, uint32_t b1) {
    asm volatile(
        "mma.sync.aligned.m16n8k16.row.col.f32.f16.f16.f32 "
        "{%0,%1,%2,%3},{%4,%5,%6,%7},{%8,%9},{%0,%1,%2,%3};"
        : "+f"(d[0]), "+f"(d[1]), "+f"(d[2]), "+f"(d[3])
        : "r"(a[0]), "r"(a[1]), "r"(a[2]), "r"(a[3]), "r"(b0), "r"(b1));
}
__device__ __forceinline__ void cpa16(void* s, const void* g) {
    uint32_t sa = (uint32_t)__cvta_generic_to_shared(s);
    asm volatile("cp.async.ca.shared.global [%0], [%1], 16;" :: "r"(sa), "l"(g));
}
__device__ __forceinline__ void cpa_commit() { asm volatile("cp.async.commit_group;"); }
__device__ __forceinline__ void cpa_wait0()  { asm volatile("cp.async.wait_group 0;" ::: "memory"); }

// -------- mask dtype detect --------
__global__ void detect_mask_kernel(const unsigned* __restrict__ m) {
    if (threadIdx.x == 0) {
        bool word = true;
        #pragma unroll
        for (int i = 0; i < 16; i++) {
            unsigned v = m[i];
            if (v != 0u && v != 1u && v != 0x3f800000u) word = false;
        }
        g_mask_word = word ? 1 : 0;
    }
}

// -------- fp32 -> fp16 round --------
__global__ void __launch_bounds__(256) round_f32(
    const float* __restrict__ x, fp16* __restrict__ h, int n)
{
    int i = (blockIdx.x * 256 + threadIdx.x) * 2;
    if (i < n) {
        float2 v = *(const float2*)(x + i);
        *(__half2*)(h + i) = __halves2half2(__float2half_rn(v.x), __float2half_rn(v.y));
    }
}
// -------- all 4 weights -> fp16 in one launch --------
#define NW (DDIM*DDIM)
__global__ void __launch_bounds__(256) round4_f32(
    const float* __restrict__ a, const float* __restrict__ b,
    const float* __restrict__ c, const float* __restrict__ d,
    fp16* __restrict__ oa, fp16* __restrict__ ob,
    fp16* __restrict__ oc, fp16* __restrict__ od)
{
    const int sel = blockIdx.x >> 11;                  // 2048 blocks per weight
    const int off = ((blockIdx.x & 2047) * 256 + threadIdx.x) * 2;
    const float* src = (sel == 0) ? a : (sel == 1) ? b : (sel == 2) ? c : d;
    fp16* dst = (sel == 0) ? oa : (sel == 1) ? ob : (sel == 2) ? oc : od;
    float2 v = *(const float2*)(src + off);
    *(__half2*)(dst + off) = __halves2half2(__float2half_rn(v.x), __float2half_rn(v.y));
}

// ---------------------------------------------------------------- fused QKV GEMM
// Single-product fp16: C = scale * (X @ W^T). One launch does q, k, v.
// blockIdx.x: [0,8)=q, [8,16)=k, [16,24)=v ; within: n0 = (bx&7)*128.
// q,k -> split-head [B,H,S,dh]; v -> transposed [B,H,dh,S].
#define GS 40
#define TSZ (128*GS)
#define QKV_SMEM (2*2*TSZ*2)   // 2 bufs x {A,B}: 40960 B

__global__ void __launch_bounds__(256, 2) gemm_qkv(
    const fp16* __restrict__ Xg,
    const fp16* __restrict__ Wq, const fp16* __restrict__ Wk,
    const fp16* __restrict__ Wv,
    fp16* __restrict__ Qo, fp16* __restrict__ Ko, fp16* __restrict__ Vo)
{
    extern __shared__ fp16 smh[];
    const int t = threadIdx.x;
    const int wid = t >> 5, lane = t & 31;
    const int lr = lane >> 2, lc = lane & 3;
    const int wsel = blockIdx.x >> 3;
    const int n0 = (blockIdx.x & 7) * 128;
    const int m0 = blockIdx.y * 128;
    const int wm = (wid >> 2) * 64, wn = (wid & 3) * 32;
    const fp16* Wg = (wsel == 0) ? Wq : (wsel == 1) ? Wk : Wv;
    const float scale = (wsel == 0) ? 0.125f : 1.f;

    float acc[4][4][4];
    #pragma unroll
    for (int i = 0; i < 4; i++)
        #pragma unroll
        for (int j = 0; j < 4; j++)
            #pragma unroll
            for (int r = 0; r < 4; r++) acc[i][j][r] = 0.f;

    auto cp_tile = [&](int buf, int k0) {
        fp16* base = smh + buf * 2 * TSZ;
        #pragma unroll
        for (int i = 0; i < 4; i++) {
            const int sub = i >> 1;          // 0=A, 1=B
            const int j = (i & 1) * 256 + t;
            const int row = j >> 2, ch = (j & 3) * 8;
            const fp16* src = (sub == 0)
                ? Xg + (size_t)(m0 + row) * DDIM + k0 + ch
                : Wg + (size_t)(n0 + row) * DDIM + k0 + ch;
            cpa16(&base[sub * TSZ + row * GS + ch], src);
        }
        cpa_commit();
    };

    cp_tile(0, 0);
    for (int c = 0; c < 32; c++) {
        cpa_wait0();
        __syncthreads();
        if (c < 31) cp_tile((c + 1) & 1, (c + 1) * 32);
        const fp16* As = smh + (c & 1) * 2 * TSZ;
        const fp16* Bs = As + TSZ;

        #pragma unroll
        for (int ks = 0; ks < 2; ks++) {
            const int kc = ks * 16 + 2 * lc;
            uint32_t ah[4][4];
            #pragma unroll
            for (int mi = 0; mi < 4; mi++) {
                const int r = wm + mi * 16 + lr;
                ah[mi][0] = lds32(As + (r    ) * GS + kc);
                ah[mi][1] = lds32(As + (r + 8) * GS + kc);
                ah[mi][2] = lds32(As + (r    ) * GS + kc + 8);
                ah[mi][3] = lds32(As + (r + 8) * GS + kc + 8);
            }
            uint32_t bh[4][2];
            #pragma unroll
            for (int ni = 0; ni < 4; ni++) {
                const int n = wn + ni * 8 + lr;
                bh[ni][0] = lds32(Bs + n * GS + kc);
                bh[ni][1] = lds32(Bs + n * GS + kc + 8);
            }
            #pragma unroll
            for (int mi = 0; mi < 4; mi++)
                #pragma unroll
                for (int ni = 0; ni < 4; ni++)
                    mma16(acc[mi][ni], ah[mi], bh[ni][0], bh[ni][1]);
        }
        __syncthreads();
    }

    // epilogue
    #pragma unroll
    for (int mi = 0; mi < 4; mi++) {
        #pragma unroll
        for (int ni = 0; ni < 4; ni++) {
            const int n = n0 + wn + ni * 8 + 2 * lc;
            #pragma unroll
            for (int rr = 0; rr < 2; rr++) {
                const int m = m0 + wm + mi * 16 + lr + rr * 8;
                const float v0 = acc[mi][ni][rr * 2 + 0] * scale;
                const float v1 = acc[mi][ni][rr * 2 + 1] * scale;
                const int b = m >> 11, s = m & (SS - 1);
                const int h = n >> 6,  dd = n & (DH - 1);
                if (wsel < 2) {
                    fp16* dst = (wsel == 0) ? Qo : Ko;
                    size_t idx = (((size_t)(b * HH + h) * SS + s) * DH) + dd;
                    *(__half2*)&dst[idx] =
                        __halves2half2(__float2half_rn(v0), __float2half_rn(v1));
                } else {
                    size_t idx = (((size_t)(b * HH + h) * DH + dd) * SS) + s;
                    Vo[idx]      = __float2half_rn(v0);
                    Vo[idx + SS] = __float2half_rn(v1);
                }
            }
        }
    }
}

// ---------------------------------------------------------------- out-proj GEMM
// 2-product: out = (Ch + Cl) @ Wo^T + bias, fp32 out.
#define GEMM_SMEM (2*3*TSZ*2)

__global__ void __launch_bounds__(256, 2) gemm_out(
    const fp16* __restrict__ Agh, const fp16* __restrict__ Agl,
    const fp16* __restrict__ Wg, const float* __restrict__ bias,
    float* __restrict__ Co)
{
    extern __shared__ fp16 smh[];
    const int t = threadIdx.x;
    const int wid = t >> 5, lane = t & 31;
    const int lr = lane >> 2, lc = lane & 3;
    const int m0 = blockIdx.y * 128, n0 = blockIdx.x * 128;
    const int wm = (wid >> 2) * 64, wn = (wid & 3) * 32;

    float acc[4][4][4];
    #pragma unroll
    for (int i = 0; i < 4; i++)
        #pragma unroll
        for (int j = 0; j < 4; j++)
            #pragma unroll
            for (int r = 0; r < 4; r++) acc[i][j][r] = 0.f;

    auto cp_tile = [&](int buf, int k0) {
        fp16* base = smh + buf * 3 * TSZ;
        #pragma unroll
        for (int i = 0; i < 6; i++) {
            const int sub = i >> 1;
            const int j = (i & 1) * 256 + t;
            const int row = j >> 2, ch = (j & 3) * 8;
            const fp16* src;
            if (sub == 0)      src = Agh + (size_t)(m0 + row) * DDIM + k0 + ch;
            else if (sub == 1) src = Agl + (size_t)(m0 + row) * DDIM + k0 + ch;
            else               src = Wg  + (size_t)(n0 + row) * DDIM + k0 + ch;
            cpa16(&base[sub * TSZ + row * GS + ch], src);
        }
        cpa_commit();
    };

    cp_tile(0, 0);
    for (int c = 0; c < 32; c++) {
        cpa_wait0();
        __syncthreads();
        if (c < 31) cp_tile((c + 1) & 1, (c + 1) * 32);
        const fp16* Ahs = smh + (c & 1) * 3 * TSZ;
        const fp16* Als = Ahs + TSZ;
        const fp16* Bs  = Ahs + 2 * TSZ;

        #pragma unroll
        for (int ks = 0; ks < 2; ks++) {
            const int kc = ks * 16 + 2 * lc;
            uint32_t ah[4][4], al[4][4];
            #pragma unroll
            for (int mi = 0; mi < 4; mi++) {
                const int r = wm + mi * 16 + lr;
                ah[mi][0] = lds32(Ahs + (r    ) * GS + kc);
                ah[mi][1] = lds32(Ahs + (r + 8) * GS + kc);
                ah[mi][2] = lds32(Ahs + (r    ) * GS + kc + 8);
                ah[mi][3] = lds32(Ahs + (r + 8) * GS + kc + 8);
                al[mi][0] = lds32(Als + (r    ) * GS + kc);
                al[mi][1] = lds32(Als + (r + 8) * GS + kc);
                al[mi][2] = lds32(Als + (r    ) * GS + kc + 8);
                al[mi][3] = lds32(Als + (r + 8) * GS + kc + 8);
            }
            uint32_t bh[4][2];
            #pragma unroll
            for (int ni = 0; ni < 4; ni++) {
                const int n = wn + ni * 8 + lr;
                bh[ni][0] = lds32(Bs + n * GS + kc);
                bh[ni][1] = lds32(Bs + n * GS + kc + 8);
            }
            #pragma unroll
            for (int mi = 0; mi < 4; mi++)
                #pragma unroll
                for (int ni = 0; ni < 4; ni++) {
                    mma16(acc[mi][ni], ah[mi], bh[ni][0], bh[ni][1]);
                    mma16(acc[mi][ni], al[mi], bh[ni][0], bh[ni][1]);
                }
        }
        __syncthreads();
    }

    #pragma unroll
    for (int mi = 0; mi < 4; mi++) {
        #pragma unroll
        for (int ni = 0; ni < 4; ni++) {
            const int n = n0 + wn + ni * 8 + 2 * lc;
            #pragma unroll
            for (int rr = 0; rr < 2; rr++) {
                const int m = m0 + wm + mi * 16 + lr + rr * 8;
                Co[(size_t)m * DDIM + n]     = acc[mi][ni][rr * 2 + 0] + bias[n];
                Co[(size_t)m * DDIM + n + 1] = acc[mi][ni][rr * 2 + 1] + bias[n + 1];
            }
        }
    }
}

// ---------------------------------------------------------------- attention
// fp16 flash attention (identical structure to the R13 kernel that passed).
#define AQ 0
#define AK(b) (128*72 + (b)*64*72)
#define AV(b) (128*72 + 2*64*72 + (b)*64*72)
#define AP (128*72 + 4*64*72)
#define AMSK_BYTE ((AP + 128*72) * 2)
#define ATT_SMEM_BYTES (AMSK_BYTE + 2*128*64)

__global__ void __launch_bounds__(256, 2) attn_hf1(
    const fp16* __restrict__ Q16, const fp16* __restrict__ K16,
    const fp16* __restrict__ V16, const uint8_t* __restrict__ maskp,
    fp16* __restrict__ CH, fp16* __restrict__ CL)
{
    extern __shared__ fp16 smh[];
    uint8_t* Mskb = (uint8_t*)smh + AMSK_BYTE;

    const int t = threadIdx.x;
    const int wid = t >> 5, lane = t & 31;
    const int lr = lane >> 2, lc = lane & 3;
    const int w16 = wid * 16;
    const int bh = blockIdx.y;
    const int b = bh >> 4, h = bh & 15;
    const int q0 = blockIdx.x * 128;
    const int mword = g_mask_word;
    const unsigned* mask32 = (const unsigned*)maskp;

    const size_t base = (size_t)bh * SS * DH;

    #pragma unroll
    for (int i = 0; i < 4; i++) {
        const int j = i * 256 + t;
        const int row = j >> 3, ch = (j & 7) * 8;
        cpa16(&smh[AQ + row * 72 + ch], Q16 + base + (size_t)(q0 + row) * DH + ch);
    }
    auto cp_kv = [&](int buf, int k0) {
        #pragma unroll
        for (int i = 0; i < 4; i++) {
            const int sub = i >> 1;
            const int j = (i & 1) * 256 + t;
            const int row = j >> 3, ch = (j & 7) * 8;
            const fp16* src;
            int doff;
            if (sub == 0) { src = K16 + base + (size_t)(k0 + row) * DH + ch; doff = AK(buf); }
            else          { src = V16 + base + (size_t)row * SS + k0 + ch;   doff = AV(buf); }
            cpa16(&smh[doff + row * 72 + ch], src);
        }
        cpa_commit();
    };
    cp_kv(0, 0);

    uint32_t mr[8];
    auto ld_mask = [&](int k0) {
        if (mword) {
            #pragma unroll
            for (int i = 0; i < 8; i++) {
                const int id = i * 256 + t;
                const int row = id >> 4, seg = id & 15;
                const unsigned* p = mask32 + ((size_t)(b * SS + q0 + row)) * SS + k0 + seg * 4;
                uint4 u = *(const uint4*)p;
                mr[i] = (u.x ? 1u : 0) | (u.y ? 0x100u : 0)
                      | (u.z ? 0x10000u : 0) | (u.w ? 0x1000000u : 0);
            }
        } else {
            #pragma unroll
            for (int i = 0; i < 2; i++) {
                const int id = i * 256 + t;
                const int row = id >> 2, seg = id & 3;
                const uint8_t* p = maskp + ((size_t)(b * SS + q0 + row)) * SS + k0 + seg * 16;
                uint4 u = *(const uint4*)p;
                mr[i * 4 + 0] = u.x; mr[i * 4 + 1] = u.y;
                mr[i * 4 + 2] = u.z; mr[i * 4 + 3] = u.w;
            }
        }
    };
    auto st_mask = [&](int buf) {
        uint32_t* Mw = (uint32_t*)(Mskb + buf * 8192);
        if (mword) {
            #pragma unroll
            for (int i = 0; i < 8; i++) {
                const int id = i * 256 + t;
                Mw[(id >> 4) * 16 + (id & 15)] = mr[i];
            }
        } else {
            #pragma unroll
            for (int i = 0; i < 2; i++) {
                const int id = i * 256 + t;
                const int row = id >> 2, seg = id & 3;
                #pragma unroll
                for (int j = 0; j < 4; j++) Mw[row * 16 + seg * 4 + j] = mr[i * 4 + j];
            }
        }
    };
    ld_mask(0);
    st_mask(0);

    float m_a = -1e30f, m_b = -1e30f, l_a = 0.f, l_b = 0.f;
    float o[8][4];
    #pragma unroll
    for (int nf = 0; nf < 8; nf++)
        #pragma unroll
        for (int r = 0; r < 4; r++) o[nf][r] = 0.f;

    for (int c = 0; c < SS / 64; c++) {
        cpa_wait0();
        __syncthreads();
        const int buf = c & 1;
        if (c + 1 < SS / 64) {
            cp_kv(buf ^ 1, (c + 1) * 64);
            ld_mask((c + 1) * 64);
        }
        const fp16* kp = smh + AK(buf);
        const fp16* vp = smh + AV(buf);
        const uint8_t* Mb = Mskb + buf * 8192;

        float s[8][4];
        #pragma unroll
        for (int nf = 0; nf < 8; nf++)
            #pragma unroll
            for (int r = 0; r < 4; r++) s[nf][r] = 0.f;
        #pragma unroll
        for (int ks = 0; ks < 4; ks++) {
            const int kc = ks * 16 + 2 * lc;
            const int r = w16 + lr;
            uint32_t q[4];
            q[0] = lds32(smh + AQ + (r    ) * 72 + kc);
            q[1] = lds32(smh + AQ + (r + 8) * 72 + kc);
            q[2] = lds32(smh + AQ + (r    ) * 72 + kc + 8);
            q[3] = lds32(smh + AQ + (r + 8) * 72 + kc + 8);
            #pragma unroll
            for (int nf = 0; nf < 8; nf++) {
                const int n = nf * 8 + lr;
                uint32_t k0v = lds32(kp + n * 72 + kc);
                uint32_t k1v = lds32(kp + n * 72 + kc + 8);
                mma16(s[nf], q, k0v, k1v);
            }
        }

        const int ra = w16 + lr, rb = ra + 8;
        float mxa = -1e30f, mxb = -1e30f;
        #pragma unroll
        for (int nf = 0; nf < 8; nf++) {
            const int c0 = nf * 8 + 2 * lc;
            if (Mb[ra * 64 + c0    ]) s[nf][0] = -1e30f;
            if (Mb[ra * 64 + c0 + 1]) s[nf][1] = -1e30f;
            if (Mb[rb * 64 + c0    ]) s[nf][2] = -1e30f;
            if (Mb[rb * 64 + c0 + 1]) s[nf][3] = -1e30f;
            mxa = fmaxf(mxa, fmaxf(s[nf][0], s[nf][1]));
            mxb = fmaxf(mxb, fmaxf(s[nf][2], s[nf][3]));
        }
        mxa = fmaxf(mxa, __shfl_xor_sync(0xFFFFFFFFu, mxa, 1));
        mxa = fmaxf(mxa, __shfl_xor_sync(0xFFFFFFFFu, mxa, 2));
        mxb = fmaxf(mxb, __shfl_xor_sync(0xFFFFFFFFu, mxb, 1));
        mxb = fmaxf(mxb, __shfl_xor_sync(0xFFFFFFFFu, mxb, 2));
        float mna = fmaxf(m_a, mxa), mnb = fmaxf(m_b, mxb);
        float ca = __expf(m_a - mna), cb = __expf(m_b - mnb);
        float sa = 0.f, sb = 0.f;
        #pragma unroll
        for (int nf = 0; nf < 8; nf++) {
            const int c0 = nf * 8 + 2 * lc;
            float p0 = (s[nf][0] <= -1e29f) ? 0.f : __expf(s[nf][0] - mna);
            float p1 = (s[nf][1] <= -1e29f) ? 0.f : __expf(s[nf][1] - mna);
            float p2 = (s[nf][2] <= -1e29f) ? 0.f : __expf(s[nf][2] - mnb);
            float p3 = (s[nf][3] <= -1e29f) ? 0.f : __expf(s[nf][3] - mnb);
            sa += p0 + p1; sb += p2 + p3;
            *(__half2*)&smh[AP + ra * 72 + c0] =
                __halves2half2(__float2half_rn(p0), __float2half_rn(p1));
            *(__half2*)&smh[AP + rb * 72 + c0] =
                __halves2half2(__float2half_rn(p2), __float2half_rn(p3));
        }
        sa += __shfl_xor_sync(0xFFFFFFFFu, sa, 1);
        sa += __shfl_xor_sync(0xFFFFFFFFu, sa, 2);
        sb += __shfl_xor_sync(0xFFFFFFFFu, sb, 1);
        sb += __shfl_xor_sync(0xFFFFFFFFu, sb, 2);
        l_a = l_a * ca + sa; l_b = l_b * cb + sb;
        m_a = mna; m_b = mnb;
        #pragma unroll
        for (int nf = 0; nf < 8; nf++) {
            o[nf][0] *= ca; o[nf][1] *= ca; o[nf][2] *= cb; o[nf][3] *= cb;
        }
        __syncwarp();

        #pragma unroll
        for (int ks = 0; ks < 4; ks++) {
            const int kc = ks * 16 + 2 * lc;
            const int r = w16 + lr;
            uint32_t ph[4];
            ph[0] = lds32(smh + AP + (r    ) * 72 + kc);
            ph[1] = lds32(smh + AP + (r + 8) * 72 + kc);
            ph[2] = lds32(smh + AP + (r    ) * 72 + kc + 8);
            ph[3] = lds32(smh + AP + (r + 8) * 72 + kc + 8);
            #pragma unroll
            for (int nf = 0; nf < 8; nf++) {
                const int n = nf * 8 + lr;
                uint32_t v0 = lds32(vp + n * 72 + kc);
                uint32_t v1 = lds32(vp + n * 72 + kc + 8);
                mma16(o[nf], ph, v0, v1);
            }
        }

        if (c + 1 < SS / 64) st_mask(buf ^ 1);
    }

    const float inva = (l_a > 0.f) ? (1.f / l_a) : 0.f;
    const float invb = (l_b > 0.f) ? (1.f / l_b) : 0.f;
    const int qa = q0 + w16 + lr, qb = qa + 8;
    #pragma unroll
    for (int nf = 0; nf < 8; nf++) {
        const int dd = h * DH + nf * 8 + 2 * lc;
        fp16 h0, l0, h1, l1;
        hsplit(o[nf][0] * inva, h0, l0); hsplit(o[nf][1] * inva, h1, l1);
        size_t ia = (size_t)(b * SS + qa) * DDIM + dd;
        *(__half2*)&CH[ia] = __halves2half2(h0, h1);
        *(__half2*)&CL[ia] = __halves2half2(l0, l1);
        hsplit(o[nf][2] * invb, h0, l0); hsplit(o[nf][3] * invb, h1, l1);
        size_t ib = (size_t)(b * SS + qb) * DDIM + dd;
        *(__half2*)&CH[ib] = __halves2half2(h0, h1);
        *(__half2*)&CL[ib] = __halves2half2(l0, l1);
    }
}

// ---------------------------------------------------------------- launcher
extern "C" void kernel_launch(void* const* d_in, const int* in_sizes, int n_in,
                              void* d_out, int out_size)
{
    const float* query = (const float*)d_in[0];
    const void*  mask  = d_in[1];
    const float* Wq    = (const float*)d_in[2];
    const float* Wk    = (const float*)d_in[3];
    const float* Wv    = (const float*)d_in[4];
    const float* Wo    = (const float*)d_in[5];
    const float* bo    = (const float*)d_in[6];
    float* out = (float*)d_out;

    fp16 *x16, *wq16, *wk16, *wv16, *wo16;
    fp16 *q16, *k16, *v16, *cl;
    cudaGetSymbolAddress((void**)&x16, g_x16);
    cudaGetSymbolAddress((void**)&wq16, g_wq16); cudaGetSymbolAddress((void**)&wk16, g_wk16);
    cudaGetSymbolAddress((void**)&wv16, g_wv16); cudaGetSymbolAddress((void**)&wo16, g_wo16);
    cudaGetSymbolAddress((void**)&q16, g_q16);   cudaGetSymbolAddress((void**)&k16, g_k16);
    cudaGetSymbolAddress((void**)&v16, g_v16);   cudaGetSymbolAddress((void**)&cl, g_cl);
    fp16* ch = x16;   // reuse: x16 is dead after gemm_qkv

    cudaFuncSetAttribute(gemm_out, cudaFuncAttributeMaxDynamicSharedMemorySize, GEMM_SMEM);
    cudaFuncSetAttribute(attn_hf1, cudaFuncAttributeMaxDynamicSharedMemorySize, ATT_SMEM_BYTES);

    detect_mask_kernel<<<1, 32>>>((const unsigned*)mask);

    const int nq = MM * DDIM;
    round_f32<<<nq / 512, 256>>>(query, x16, nq);
    round4_f32<<<4 * NW / 512, 256>>>(Wq, Wk, Wv, Wo, wq16, wk16, wv16, wo16);

    gemm_qkv<<<dim3(24, MM / 128), 256, QKV_SMEM>>>(
        x16, wq16, wk16, wv16, q16, k16, v16);

    attn_hf1<<<dim3(SS / 128, BB * HH), 256, ATT_SMEM_BYTES>>>(
        q16, k16, v16, (const uint8_t*)mask, ch, cl);

    gemm_out<<<dim3(DDIM / 128, MM / 128), 256, GEMM_SMEM>>>(ch, cl, wo16, bo, out);
}